// round 2
// baseline (speedup 1.0000x reference)
#include <cuda_runtime.h>
#include <math.h>

// Problem constants (fixed by the reference):
//   B=1, T_OUT=8, L=512 -> S=4096 tokens, D=512, H=8 heads, hd=64
#define S_TOK   4096
#define D_MODEL 512
#define NH      8
#define HD      64

// Scratch (device globals: allocation-free, graph-safe). 32 MB total.
__device__ float g_q[NH * S_TOK * HD];   // per-head [h][s][hd], CAPE'd, pre-scaled
__device__ float g_k[NH * S_TOK * HD];   // per-head [h][s][hd], CAPE'd
__device__ float g_v[NH * S_TOK * HD];   // per-head [h][s][hd]
__device__ float g_o[S_TOK * D_MODEL];   // attention output, (S, D) row-major

// ============================================================================
// Kernel 1: QKV projection + CAPE epilogue.
//   q/k/v[s][n] = sum_k x[s][k] * W[k][n]; then for q,k: groups of 4 columns
//   rotated by the 4x4 frame matrix P (p_out_inv for q, p_out for k).
//   Tile: BM=128, BN=64, BK=32; 256 threads; 8x4 micro-tile.
//   blockIdx.z selects q/k/v.
// ============================================================================
__global__ void __launch_bounds__(256) qkv_kernel(
    const float* __restrict__ x,
    const float* __restrict__ Wq, const float* __restrict__ Wk,
    const float* __restrict__ Wv,
    const float* __restrict__ p_out, const float* __restrict__ p_out_inv)
{
    __shared__ float a_s[32][132];  // [kk][m], padded (transposed A)
    __shared__ float b_s[32][68];   // [kk][n], padded

    const int mode = blockIdx.z;   // 0=q, 1=k, 2=v
    const float* __restrict__ W   = (mode == 0) ? Wq : (mode == 1) ? Wk : Wv;
    float* __restrict__ out       = (mode == 0) ? g_q : (mode == 1) ? g_k : g_v;
    const float* __restrict__ Pm  = (mode == 0) ? p_out_inv : p_out;

    const int tid = threadIdx.x;
    const int tx  = tid & 15;          // 0..15 -> 4 output cols
    const int ty  = tid >> 4;          // 0..15 -> 8 output rows
    const int m0  = blockIdx.y * 128;
    const int n0  = blockIdx.x * 64;

    // Loader mapping
    const int arow = tid >> 1;             // 0..127
    const int acol = (tid & 1) * 16;       // 0 or 16
    const int brow = tid >> 3;             // 0..31
    const int bcol = (tid & 7) * 8;        // 0..56

    float acc[8][4];
#pragma unroll
    for (int i = 0; i < 8; i++)
#pragma unroll
        for (int j = 0; j < 4; j++) acc[i][j] = 0.f;

    for (int k0 = 0; k0 < D_MODEL; k0 += 32) {
        float4 av[4], bv[2];
        const float4* ga = reinterpret_cast<const float4*>(
            x + (size_t)(m0 + arow) * D_MODEL + k0 + acol);
        av[0] = ga[0]; av[1] = ga[1]; av[2] = ga[2]; av[3] = ga[3];
        const float4* gb = reinterpret_cast<const float4*>(
            W + (size_t)(k0 + brow) * D_MODEL + n0 + bcol);
        bv[0] = gb[0]; bv[1] = gb[1];

        __syncthreads();
#pragma unroll
        for (int u = 0; u < 4; u++) {
            a_s[acol + 4*u + 0][arow] = av[u].x;
            a_s[acol + 4*u + 1][arow] = av[u].y;
            a_s[acol + 4*u + 2][arow] = av[u].z;
            a_s[acol + 4*u + 3][arow] = av[u].w;
        }
        *reinterpret_cast<float4*>(&b_s[brow][bcol])     = bv[0];
        *reinterpret_cast<float4*>(&b_s[brow][bcol + 4]) = bv[1];
        __syncthreads();

#pragma unroll 8
        for (int kk = 0; kk < 32; kk++) {
            float4 a0 = *reinterpret_cast<const float4*>(&a_s[kk][ty * 8]);
            float4 a1 = *reinterpret_cast<const float4*>(&a_s[kk][ty * 8 + 4]);
            float4 b0 = *reinterpret_cast<const float4*>(&b_s[kk][tx * 4]);
            float ar[8] = {a0.x, a0.y, a0.z, a0.w, a1.x, a1.y, a1.z, a1.w};
            float br[4] = {b0.x, b0.y, b0.z, b0.w};
#pragma unroll
            for (int i = 0; i < 8; i++)
#pragma unroll
                for (int j = 0; j < 4; j++)
                    acc[i][j] = fmaf(ar[i], br[j], acc[i][j]);
        }
    }

    // CAPE epilogue (q and k only). All 128 rows of this tile are in one frame.
    if (mode < 2) {
        const float* P = Pm + (m0 >> 9) * 16;   // frame = m0/512; P is [4][4]
        float pm[16];
#pragma unroll
        for (int t = 0; t < 16; t++) pm[t] = P[t];
#pragma unroll
        for (int i = 0; i < 8; i++) {
            float r0 = acc[i][0]*pm[0]  + acc[i][1]*pm[4]  + acc[i][2]*pm[8]  + acc[i][3]*pm[12];
            float r1 = acc[i][0]*pm[1]  + acc[i][1]*pm[5]  + acc[i][2]*pm[9]  + acc[i][3]*pm[13];
            float r2 = acc[i][0]*pm[2]  + acc[i][1]*pm[6]  + acc[i][2]*pm[10] + acc[i][3]*pm[14];
            float r3 = acc[i][0]*pm[3]  + acc[i][1]*pm[7]  + acc[i][2]*pm[11] + acc[i][3]*pm[15];
            acc[i][0] = r0; acc[i][1] = r1; acc[i][2] = r2; acc[i][3] = r3;
        }
    }
    // Fold the softmax scale (hd^-0.5 = 0.125) into q.
    if (mode == 0) {
#pragma unroll
        for (int i = 0; i < 8; i++)
#pragma unroll
            for (int j = 0; j < 4; j++) acc[i][j] *= 0.125f;
    }

    // Store into per-head layout [h][s][hd]
    const int n = n0 + tx * 4;
    const int h = n >> 6;
    const int c = n & 63;
#pragma unroll
    for (int i = 0; i < 8; i++) {
        const int m = m0 + ty * 8 + i;
        *reinterpret_cast<float4*>(out + ((size_t)h * S_TOK + m) * HD + c) =
            make_float4(acc[i][0], acc[i][1], acc[i][2], acc[i][3]);
    }
}

// ============================================================================
// Kernel 2: flash attention, fp32. One block = (128 queries) x (one head).
//   Score tile 128x128, 256 threads, 8x8 micro-tile; online softmax with
//   shuffle row-reductions; P staged in smem for the PV GEMM.
//   Dynamic smem: 169,984 B -> 1 block/SM.
// ============================================================================
#define ATTN_SMEM_BYTES ((2 * 64 * 132 + 128 * 68 + 128 * 132) * 4)

__global__ void __launch_bounds__(256) attn_kernel()
{
    extern __shared__ float sm[];
    float* q_s = sm;                          // [64][132]  q^T (kk, i)
    float* k_s = sm + 64 * 132;               // [64][132]  k^T (kk, j)
    float* v_s = sm + 2 * 64 * 132;           // [128][68]  (j, c)
    float* p_s = sm + 2 * 64 * 132 + 128*68;  // [128][132] p^T (j, i)

    const int tid = threadIdx.x;
    const int tx  = tid & 15;
    const int ty  = tid >> 4;
    const int h   = blockIdx.y;
    const int m0  = blockIdx.x * 128;

    const float* __restrict__ qg = g_q + (size_t)h * S_TOK * HD;
    const float* __restrict__ kg = g_k + (size_t)h * S_TOK * HD;
    const float* __restrict__ vg = g_v + (size_t)h * S_TOK * HD;

    // Load Q tile, transposed (scale already folded in by qkv_kernel).
    {
        const int i  = tid >> 1;
        const int c0 = (tid & 1) * 32;
        const float4* src = reinterpret_cast<const float4*>(
            qg + (size_t)(m0 + i) * HD + c0);
#pragma unroll
        for (int u = 0; u < 8; u++) {
            float4 v = src[u];
            const int c = c0 + 4 * u;
            q_s[(c + 0) * 132 + i] = v.x;
            q_s[(c + 1) * 132 + i] = v.y;
            q_s[(c + 2) * 132 + i] = v.z;
            q_s[(c + 3) * 132 + i] = v.w;
        }
    }

    float m_i[8], l_i[8], o_acc[8][4];
#pragma unroll
    for (int i = 0; i < 8; i++) {
        m_i[i] = -1e30f;
        l_i[i] = 0.f;
#pragma unroll
        for (int c = 0; c < 4; c++) o_acc[i][c] = 0.f;
    }

    for (int kt = 0; kt < S_TOK / 128; kt++) {
        __syncthreads();  // prev PV done before overwriting k_s/v_s/p_s
        {
            const int j  = tid >> 1;
            const int c0 = (tid & 1) * 32;
            const float4* sk = reinterpret_cast<const float4*>(
                kg + (size_t)(kt * 128 + j) * HD + c0);
#pragma unroll
            for (int u = 0; u < 8; u++) {
                float4 v = sk[u];
                const int c = c0 + 4 * u;
                k_s[(c + 0) * 132 + j] = v.x;
                k_s[(c + 1) * 132 + j] = v.y;
                k_s[(c + 2) * 132 + j] = v.z;
                k_s[(c + 3) * 132 + j] = v.w;
            }
            const float4* sv = reinterpret_cast<const float4*>(
                vg + (size_t)(kt * 128 + j) * HD + c0);
            float4* dv = reinterpret_cast<float4*>(v_s + j * 68 + c0);
#pragma unroll
            for (int u = 0; u < 8; u++) dv[u] = sv[u];
        }
        __syncthreads();

        // ---- S = Q K^T (scaled) ----
        float s[8][8];
#pragma unroll
        for (int i = 0; i < 8; i++)
#pragma unroll
            for (int j = 0; j < 8; j++) s[i][j] = 0.f;

#pragma unroll 4
        for (int kk = 0; kk < 64; kk++) {
            float4 a0 = *reinterpret_cast<const float4*>(&q_s[kk * 132 + ty * 8]);
            float4 a1 = *reinterpret_cast<const float4*>(&q_s[kk * 132 + ty * 8 + 4]);
            float4 b0 = *reinterpret_cast<const float4*>(&k_s[kk * 132 + tx * 8]);
            float4 b1 = *reinterpret_cast<const float4*>(&k_s[kk * 132 + tx * 8 + 4]);
            float ar[8] = {a0.x, a0.y, a0.z, a0.w, a1.x, a1.y, a1.z, a1.w};
            float br[8] = {b0.x, b0.y, b0.z, b0.w, b1.x, b1.y, b1.z, b1.w};
#pragma unroll
            for (int i = 0; i < 8; i++)
#pragma unroll
                for (int j = 0; j < 8; j++)
                    s[i][j] = fmaf(ar[i], br[j], s[i][j]);
        }

        // ---- online softmax (row stats across the 16 tx lanes) ----
#pragma unroll
        for (int i = 0; i < 8; i++) {
            float mloc = s[i][0];
#pragma unroll
            for (int j = 1; j < 8; j++) mloc = fmaxf(mloc, s[i][j]);
#pragma unroll
            for (int msk = 1; msk < 16; msk <<= 1)
                mloc = fmaxf(mloc, __shfl_xor_sync(0xffffffffu, mloc, msk));
            const float mnew  = fmaxf(m_i[i], mloc);
            const float alpha = __expf(m_i[i] - mnew);
            m_i[i] = mnew;
            float rs = 0.f;
#pragma unroll
            for (int j = 0; j < 8; j++) {
                const float p = __expf(s[i][j] - mnew);
                s[i][j] = p;
                rs += p;
            }
#pragma unroll
            for (int msk = 1; msk < 16; msk <<= 1)
                rs += __shfl_xor_sync(0xffffffffu, rs, msk);
            l_i[i] = l_i[i] * alpha + rs;
#pragma unroll
            for (int c = 0; c < 4; c++) o_acc[i][c] *= alpha;
        }

        // ---- stage P (transposed) for the PV GEMM ----
#pragma unroll
        for (int jj = 0; jj < 8; jj++) {
            *reinterpret_cast<float4*>(&p_s[(tx * 8 + jj) * 132 + ty * 8]) =
                make_float4(s[0][jj], s[1][jj], s[2][jj], s[3][jj]);
            *reinterpret_cast<float4*>(&p_s[(tx * 8 + jj) * 132 + ty * 8 + 4]) =
                make_float4(s[4][jj], s[5][jj], s[6][jj], s[7][jj]);
        }
        __syncthreads();

        // ---- O += P V ----
#pragma unroll 4
        for (int j = 0; j < 128; j++) {
            float4 p0 = *reinterpret_cast<const float4*>(&p_s[j * 132 + ty * 8]);
            float4 p1 = *reinterpret_cast<const float4*>(&p_s[j * 132 + ty * 8 + 4]);
            float4 vv = *reinterpret_cast<const float4*>(&v_s[j * 68 + tx * 4]);
            float pr[8] = {p0.x, p0.y, p0.z, p0.w, p1.x, p1.y, p1.z, p1.w};
            float vr[4] = {vv.x, vv.y, vv.z, vv.w};
#pragma unroll
            for (int i = 0; i < 8; i++)
#pragma unroll
                for (int c = 0; c < 4; c++)
                    o_acc[i][c] = fmaf(pr[i], vr[c], o_acc[i][c]);
        }
    }

    // Normalize + store to (S, D) layout.
#pragma unroll
    for (int i = 0; i < 8; i++) {
        const float inv = 1.0f / l_i[i];
        const int m = m0 + ty * 8 + i;
        *reinterpret_cast<float4*>(g_o + (size_t)m * D_MODEL + h * HD + tx * 4) =
            make_float4(o_acc[i][0] * inv, o_acc[i][1] * inv,
                        o_acc[i][2] * inv, o_acc[i][3] * inv);
    }
}

// ============================================================================
// Kernel 3: output projection + bias + residual.
//   out[m][n] = sum_k o[m][k] * Wo[k][n] + bo[n] + hidden_states[m][n]
// ============================================================================
__global__ void __launch_bounds__(256) proj_kernel(
    const float* __restrict__ Wo, const float* __restrict__ bo,
    const float* __restrict__ hs, float* __restrict__ outp)
{
    __shared__ float a_s[32][132];
    __shared__ float b_s[32][68];

    const int tid = threadIdx.x;
    const int tx  = tid & 15;
    const int ty  = tid >> 4;
    const int m0  = blockIdx.y * 128;
    const int n0  = blockIdx.x * 64;

    const int arow = tid >> 1;
    const int acol = (tid & 1) * 16;
    const int brow = tid >> 3;
    const int bcol = (tid & 7) * 8;

    float acc[8][4];
#pragma unroll
    for (int i = 0; i < 8; i++)
#pragma unroll
        for (int j = 0; j < 4; j++) acc[i][j] = 0.f;

    for (int k0 = 0; k0 < D_MODEL; k0 += 32) {
        float4 av[4], bv[2];
        const float4* ga = reinterpret_cast<const float4*>(
            g_o + (size_t)(m0 + arow) * D_MODEL + k0 + acol);
        av[0] = ga[0]; av[1] = ga[1]; av[2] = ga[2]; av[3] = ga[3];
        const float4* gb = reinterpret_cast<const float4*>(
            Wo + (size_t)(k0 + brow) * D_MODEL + n0 + bcol);
        bv[0] = gb[0]; bv[1] = gb[1];

        __syncthreads();
#pragma unroll
        for (int u = 0; u < 4; u++) {
            a_s[acol + 4*u + 0][arow] = av[u].x;
            a_s[acol + 4*u + 1][arow] = av[u].y;
            a_s[acol + 4*u + 2][arow] = av[u].z;
            a_s[acol + 4*u + 3][arow] = av[u].w;
        }
        *reinterpret_cast<float4*>(&b_s[brow][bcol])     = bv[0];
        *reinterpret_cast<float4*>(&b_s[brow][bcol + 4]) = bv[1];
        __syncthreads();

#pragma unroll 8
        for (int kk = 0; kk < 32; kk++) {
            float4 a0 = *reinterpret_cast<const float4*>(&a_s[kk][ty * 8]);
            float4 a1 = *reinterpret_cast<const float4*>(&a_s[kk][ty * 8 + 4]);
            float4 b0 = *reinterpret_cast<const float4*>(&b_s[kk][tx * 4]);
            float ar[8] = {a0.x, a0.y, a0.z, a0.w, a1.x, a1.y, a1.z, a1.w};
            float br[4] = {b0.x, b0.y, b0.z, b0.w};
#pragma unroll
            for (int i = 0; i < 8; i++)
#pragma unroll
                for (int j = 0; j < 4; j++)
                    acc[i][j] = fmaf(ar[i], br[j], acc[i][j]);
        }
    }

    const int n = n0 + tx * 4;
    const float4 bb = *reinterpret_cast<const float4*>(bo + n);
#pragma unroll
    for (int i = 0; i < 8; i++) {
        const int m = m0 + ty * 8 + i;
        const float4 res = *reinterpret_cast<const float4*>(
            hs + (size_t)m * D_MODEL + n);
        *reinterpret_cast<float4*>(outp + (size_t)m * D_MODEL + n) =
            make_float4(acc[i][0] + bb.x + res.x,
                        acc[i][1] + bb.y + res.y,
                        acc[i][2] + bb.z + res.z,
                        acc[i][3] + bb.w + res.w);
    }
}

// ============================================================================
// Launch
// ============================================================================
extern "C" void kernel_launch(void* const* d_in, const int* in_sizes, int n_in,
                              void* d_out, int out_size)
{
    const float* hs        = (const float*)d_in[0];
    const float* p_out     = (const float*)d_in[1];
    const float* p_out_inv = (const float*)d_in[2];
    const float* Wq        = (const float*)d_in[3];
    const float* Wk        = (const float*)d_in[4];
    const float* Wv        = (const float*)d_in[5];
    const float* Wo        = (const float*)d_in[6];
    const float* bo        = (const float*)d_in[7];
    float* out             = (float*)d_out;

    // Opt-in to >48KB dynamic smem for the attention kernel (idempotent,
    // host-side attribute set; not a stream op, not an allocation).
    cudaFuncSetAttribute(attn_kernel,
                         cudaFuncAttributeMaxDynamicSharedMemorySize,
                         ATTN_SMEM_BYTES);

    qkv_kernel<<<dim3(8, 32, 3), 256>>>(hs, Wq, Wk, Wv, p_out, p_out_inv);
    attn_kernel<<<dim3(32, 8), 256, ATTN_SMEM_BYTES>>>();
    proj_kernel<<<dim3(8, 32), 256>>>(Wo, bo, hs, out);
}

// round 6
// speedup vs baseline: 3.2416x; 3.2416x over previous
#include <cuda_runtime.h>
#include <cuda_bf16.h>
#include <cstdint>
#include <stdint.h>
#include <math.h>

// Problem constants (fixed by the reference):
//   B=1, T_OUT=8, L=512 -> S=4096 tokens, D=512, H=8 heads, hd=64
#define S_TOK   4096
#define D_MODEL 512
#define NH      8
#define HD      64

// Scratch (device globals: allocation-free, graph-safe).
__device__ __nv_bfloat16 g_qb[NH * S_TOK * HD];  // [h][s][hd], CAPE'd, pre-scaled
__device__ __nv_bfloat16 g_kb[NH * S_TOK * HD];  // [h][s][hd], CAPE'd
__device__ __nv_bfloat16 g_vb[NH * S_TOK * HD];  // [h][s][hd]
__device__ float         g_o [S_TOK * D_MODEL];  // attention output, (S, D) fp32

// ----------------------------------------------------------------------------
// PTX helpers: ldmatrix + bf16 mma (fp32 accum)
// ----------------------------------------------------------------------------
__device__ __forceinline__ uint32_t smem_u32(const void* p) {
    return (uint32_t)__cvta_generic_to_shared(p);
}
__device__ __forceinline__ void ldsm_x4(uint32_t* r, uint32_t a) {
    asm volatile("ldmatrix.sync.aligned.m8n8.x4.shared.b16 {%0,%1,%2,%3}, [%4];"
                 : "=r"(r[0]), "=r"(r[1]), "=r"(r[2]), "=r"(r[3]) : "r"(a));
}
__device__ __forceinline__ void ldsm_x4_t(uint32_t* r, uint32_t a) {
    asm volatile("ldmatrix.sync.aligned.m8n8.x4.trans.shared.b16 {%0,%1,%2,%3}, [%4];"
                 : "=r"(r[0]), "=r"(r[1]), "=r"(r[2]), "=r"(r[3]) : "r"(a));
}
__device__ __forceinline__ void mma_bf16(float* c, const uint32_t* a,
                                         uint32_t b0, uint32_t b1) {
    asm volatile(
        "mma.sync.aligned.m16n8k16.row.col.f32.bf16.bf16.f32 "
        "{%0,%1,%2,%3}, {%4,%5,%6,%7}, {%8,%9}, {%0,%1,%2,%3};"
        : "+f"(c[0]), "+f"(c[1]), "+f"(c[2]), "+f"(c[3])
        : "r"(a[0]), "r"(a[1]), "r"(a[2]), "r"(a[3]), "r"(b0), "r"(b1));
}
__device__ __forceinline__ uint32_t pack_bf16x2(float a, float b) {
    __nv_bfloat162 t = __floats2bfloat162_rn(a, b);
    return *reinterpret_cast<uint32_t*>(&t);
}

// ============================================================================
// Kernel 1: QKV projection + CAPE epilogue -> bf16 per-head q/k/v.
//   Tile: BM=128, BN=64, BK=32; 256 threads; 8x4 micro-tile; blockIdx.z = q/k/v
// ============================================================================
__global__ void __launch_bounds__(256) qkv_kernel(
    const float* __restrict__ x,
    const float* __restrict__ Wq, const float* __restrict__ Wk,
    const float* __restrict__ Wv,
    const float* __restrict__ p_out, const float* __restrict__ p_out_inv)
{
    __shared__ float a_s[32][132];  // [kk][m], padded (transposed A)
    __shared__ float b_s[32][68];   // [kk][n], padded

    const int mode = blockIdx.z;   // 0=q, 1=k, 2=v
    const float* __restrict__ W  = (mode == 0) ? Wq : (mode == 1) ? Wk : Wv;
    __nv_bfloat16* __restrict__ out =
        (mode == 0) ? g_qb : (mode == 1) ? g_kb : g_vb;
    const float* __restrict__ Pm = (mode == 0) ? p_out_inv : p_out;

    const int tid = threadIdx.x;
    const int tx  = tid & 15;
    const int ty  = tid >> 4;
    const int m0  = blockIdx.y * 128;
    const int n0  = blockIdx.x * 64;

    const int arow = tid >> 1;
    const int acol = (tid & 1) * 16;
    const int brow = tid >> 3;
    const int bcol = (tid & 7) * 8;

    float acc[8][4];
#pragma unroll
    for (int i = 0; i < 8; i++)
#pragma unroll
        for (int j = 0; j < 4; j++) acc[i][j] = 0.f;

    for (int k0 = 0; k0 < D_MODEL; k0 += 32) {
        float4 av[4], bv[2];
        const float4* ga = reinterpret_cast<const float4*>(
            x + (size_t)(m0 + arow) * D_MODEL + k0 + acol);
        av[0] = ga[0]; av[1] = ga[1]; av[2] = ga[2]; av[3] = ga[3];
        const float4* gb = reinterpret_cast<const float4*>(
            W + (size_t)(k0 + brow) * D_MODEL + n0 + bcol);
        bv[0] = gb[0]; bv[1] = gb[1];

        __syncthreads();
#pragma unroll
        for (int u = 0; u < 4; u++) {
            a_s[acol + 4*u + 0][arow] = av[u].x;
            a_s[acol + 4*u + 1][arow] = av[u].y;
            a_s[acol + 4*u + 2][arow] = av[u].z;
            a_s[acol + 4*u + 3][arow] = av[u].w;
        }
        *reinterpret_cast<float4*>(&b_s[brow][bcol])     = bv[0];
        *reinterpret_cast<float4*>(&b_s[brow][bcol + 4]) = bv[1];
        __syncthreads();

#pragma unroll 8
        for (int kk = 0; kk < 32; kk++) {
            float4 a0 = *reinterpret_cast<const float4*>(&a_s[kk][ty * 8]);
            float4 a1 = *reinterpret_cast<const float4*>(&a_s[kk][ty * 8 + 4]);
            float4 b0 = *reinterpret_cast<const float4*>(&b_s[kk][tx * 4]);
            float ar[8] = {a0.x, a0.y, a0.z, a0.w, a1.x, a1.y, a1.z, a1.w};
            float br[4] = {b0.x, b0.y, b0.z, b0.w};
#pragma unroll
            for (int i = 0; i < 8; i++)
#pragma unroll
                for (int j = 0; j < 4; j++)
                    acc[i][j] = fmaf(ar[i], br[j], acc[i][j]);
        }
    }

    // CAPE epilogue (q and k only). 128-row tile sits inside one 512-row frame.
    if (mode < 2) {
        const float* P = Pm + (m0 >> 9) * 16;
        float pm[16];
#pragma unroll
        for (int t = 0; t < 16; t++) pm[t] = P[t];
#pragma unroll
        for (int i = 0; i < 8; i++) {
            float r0 = acc[i][0]*pm[0]  + acc[i][1]*pm[4]  + acc[i][2]*pm[8]  + acc[i][3]*pm[12];
            float r1 = acc[i][0]*pm[1]  + acc[i][1]*pm[5]  + acc[i][2]*pm[9]  + acc[i][3]*pm[13];
            float r2 = acc[i][0]*pm[2]  + acc[i][1]*pm[6]  + acc[i][2]*pm[10] + acc[i][3]*pm[14];
            float r3 = acc[i][0]*pm[3]  + acc[i][1]*pm[7]  + acc[i][2]*pm[11] + acc[i][3]*pm[15];
            acc[i][0] = r0; acc[i][1] = r1; acc[i][2] = r2; acc[i][3] = r3;
        }
    }
    if (mode == 0) {   // fold softmax scale hd^-0.5 = 0.125 into q
#pragma unroll
        for (int i = 0; i < 8; i++)
#pragma unroll
            for (int j = 0; j < 4; j++) acc[i][j] *= 0.125f;
    }

    // Store bf16 into per-head layout [h][s][hd]
    const int n = n0 + tx * 4;
    const int h = n >> 6;
    const int c = n & 63;
#pragma unroll
    for (int i = 0; i < 8; i++) {
        const int m = m0 + ty * 8 + i;
        uint2 u;
        u.x = pack_bf16x2(acc[i][0], acc[i][1]);
        u.y = pack_bf16x2(acc[i][2], acc[i][3]);
        *reinterpret_cast<uint2*>(out + ((size_t)h * S_TOK + m) * HD + c) = u;
    }
}

// ============================================================================
// Kernel 2: flash attention, bf16 tensor-core (mma.sync m16n8k16).
//   One CTA = 128 q-rows x 1 head; 8 warps x 16 rows; Bc = 128.
//   Q A-frags register-resident; K via ldmatrix (non-trans: hd contiguous),
//   V via ldmatrix.trans; P handed QK^T C-frags -> PV A-frags in registers.
// ============================================================================
__global__ void __launch_bounds__(256, 1) attn_kernel()
{
    __shared__ __nv_bfloat16 q_s[128 * 64];
    __shared__ __nv_bfloat16 k_s[128 * 64];
    __shared__ __nv_bfloat16 v_s[128 * 64];

    const int tid  = threadIdx.x;
    const int lane = tid & 31;
    const int w    = tid >> 5;          // warp 0..7 -> rows w*16..w*16+15
    const int h    = blockIdx.y;
    const int m0   = blockIdx.x * 128;

    const __nv_bfloat16* __restrict__ qg = g_qb + (size_t)h * S_TOK * HD;
    const __nv_bfloat16* __restrict__ kg = g_kb + (size_t)h * S_TOK * HD;
    const __nv_bfloat16* __restrict__ vg = g_vb + (size_t)h * S_TOK * HD;

    // ---- load Q tile (swizzled: 16B chunk index ^= row&7) ----
#pragma unroll
    for (int u = 0; u < 4; u++) {
        const int gid = u * 256 + tid;          // 0..1023 chunks
        const int row = gid >> 3;
        const int c8  = gid & 7;
        uint4 d = *reinterpret_cast<const uint4*>(
            qg + (size_t)(m0 + row) * HD + c8 * 8);
        *reinterpret_cast<uint4*>(q_s + row * 64 + ((c8 ^ (row & 7)) << 3)) = d;
    }
    __syncthreads();

    // ---- Q A-fragments: m16 x k64 = 4 k-tiles, register resident ----
    uint32_t qa[4][4];
    {
        const int mi = lane >> 3, rr = lane & 7;
        const int row = w * 16 + ((mi & 1) << 3) + rr;
#pragma unroll
        for (int kt = 0; kt < 4; kt++) {
            const int ch = (kt * 2 + (mi >> 1)) ^ (row & 7);
            ldsm_x4(qa[kt], smem_u32(q_s + row * 64 + ch * 8));
        }
    }

    float m_i0 = -1e30f, m_i1 = -1e30f, l0 = 0.f, l1 = 0.f;
    float of[8][4];
#pragma unroll
    for (int nt = 0; nt < 8; nt++)
#pragma unroll
        for (int c = 0; c < 4; c++) of[nt][c] = 0.f;

    for (int it = 0; it < S_TOK / 128; it++) {
        __syncthreads();  // all warps done with previous k_s/v_s
        {
            const __nv_bfloat16* ks = kg + (size_t)(it * 128) * HD;
            const __nv_bfloat16* vs = vg + (size_t)(it * 128) * HD;
#pragma unroll
            for (int u = 0; u < 4; u++) {
                const int gid = u * 256 + tid;
                const int row = gid >> 3;
                const int c8  = gid & 7;
                const int so  = row * 64 + ((c8 ^ (row & 7)) << 3);
                uint4 dk = *reinterpret_cast<const uint4*>(ks + row * 64 + c8 * 8);
                uint4 dv = *reinterpret_cast<const uint4*>(vs + row * 64 + c8 * 8);
                *reinterpret_cast<uint4*>(k_s + so) = dk;
                *reinterpret_cast<uint4*>(v_s + so) = dv;
            }
        }
        __syncthreads();

        // ---- S = Q K^T : 16 n-tiles (8 cols each) x 4 k-steps ----
        // K smem is [token][hd]; hd (mma-k) is contiguous -> NON-trans ldmatrix
        // yields B frags (pair along k, n = lane/4) directly.
        float sf[16][4];
#pragma unroll
        for (int nt = 0; nt < 16; nt++)
#pragma unroll
            for (int c = 0; c < 4; c++) sf[nt][c] = 0.f;

        {
            const int j = lane >> 3, rr = lane & 7;
#pragma unroll
            for (int nt = 0; nt < 16; nt++) {
                const int srow = nt * 8 + rr;
                uint32_t b[8];
                const int ch0 = (j)     ^ (srow & 7);
                const int ch1 = (4 + j) ^ (srow & 7);
                ldsm_x4(b,     smem_u32(k_s + srow * 64 + ch0 * 8));
                ldsm_x4(b + 4, smem_u32(k_s + srow * 64 + ch1 * 8));
                mma_bf16(sf[nt], qa[0], b[0], b[1]);
                mma_bf16(sf[nt], qa[1], b[2], b[3]);
                mma_bf16(sf[nt], qa[2], b[4], b[5]);
                mma_bf16(sf[nt], qa[3], b[6], b[7]);
            }
        }

        // ---- online softmax (rows lane/4 and lane/4+8; quad = lanes xor 1,2) --
        float mx0 = sf[0][0], mx1 = sf[0][2];
#pragma unroll
        for (int nt = 0; nt < 16; nt++) {
            mx0 = fmaxf(mx0, fmaxf(sf[nt][0], sf[nt][1]));
            mx1 = fmaxf(mx1, fmaxf(sf[nt][2], sf[nt][3]));
        }
        mx0 = fmaxf(mx0, __shfl_xor_sync(0xffffffffu, mx0, 1));
        mx0 = fmaxf(mx0, __shfl_xor_sync(0xffffffffu, mx0, 2));
        mx1 = fmaxf(mx1, __shfl_xor_sync(0xffffffffu, mx1, 1));
        mx1 = fmaxf(mx1, __shfl_xor_sync(0xffffffffu, mx1, 2));

        const float mn0 = fmaxf(m_i0, mx0);
        const float mn1 = fmaxf(m_i1, mx1);
        const float al0 = __expf(m_i0 - mn0);
        const float al1 = __expf(m_i1 - mn1);
        m_i0 = mn0; m_i1 = mn1;

        float rs0 = 0.f, rs1 = 0.f;
        uint32_t pa[8][4];   // P A-frags for PV (k = 128 -> 8 k-tiles)
#pragma unroll
        for (int nt = 0; nt < 16; nt++) {
            const float e0 = __expf(sf[nt][0] - mn0);
            const float e1 = __expf(sf[nt][1] - mn0);
            const float e2 = __expf(sf[nt][2] - mn1);
            const float e3 = __expf(sf[nt][3] - mn1);
            rs0 += e0 + e1; rs1 += e2 + e3;
            const uint32_t p01 = pack_bf16x2(e0, e1);
            const uint32_t p23 = pack_bf16x2(e2, e3);
            const int jt = nt >> 1;
            if ((nt & 1) == 0) { pa[jt][0] = p01; pa[jt][1] = p23; }
            else               { pa[jt][2] = p01; pa[jt][3] = p23; }
        }
        rs0 += __shfl_xor_sync(0xffffffffu, rs0, 1);
        rs0 += __shfl_xor_sync(0xffffffffu, rs0, 2);
        rs1 += __shfl_xor_sync(0xffffffffu, rs1, 1);
        rs1 += __shfl_xor_sync(0xffffffffu, rs1, 2);
        l0 = l0 * al0 + rs0;
        l1 = l1 * al1 + rs1;

#pragma unroll
        for (int nt = 0; nt < 8; nt++) {
            of[nt][0] *= al0; of[nt][1] *= al0;
            of[nt][2] *= al1; of[nt][3] *= al1;
        }

        // ---- O += P V : k = 128 in 4 chunks of 32 ----
        // V smem [token][hd]; mma-k = token = memory rows -> trans ldmatrix.
        {
            const int j = lane >> 3, rr = lane & 7;
#pragma unroll
            for (int kt2 = 0; kt2 < 4; kt2++) {
                const int vrow = kt2 * 32 + j * 8 + rr;
#pragma unroll
                for (int nt = 0; nt < 8; nt++) {
                    uint32_t vb[4];
                    const int ch = nt ^ (vrow & 7);
                    ldsm_x4_t(vb, smem_u32(v_s + vrow * 64 + ch * 8));
                    mma_bf16(of[nt], pa[2 * kt2],     vb[0], vb[1]);
                    mma_bf16(of[nt], pa[2 * kt2 + 1], vb[2], vb[3]);
                }
            }
        }
    }

    // ---- normalize + store to (S, D) fp32 ----
    const float inv0 = 1.0f / l0;
    const float inv1 = 1.0f / l1;
    const int row0 = m0 + w * 16 + (lane >> 2);
    const int row1 = row0 + 8;
    const int cbase = h * HD + (lane & 3) * 2;
#pragma unroll
    for (int nt = 0; nt < 8; nt++) {
        const int col = cbase + nt * 8;
        *reinterpret_cast<float2*>(g_o + (size_t)row0 * D_MODEL + col) =
            make_float2(of[nt][0] * inv0, of[nt][1] * inv0);
        *reinterpret_cast<float2*>(g_o + (size_t)row1 * D_MODEL + col) =
            make_float2(of[nt][2] * inv1, of[nt][3] * inv1);
    }
}

// ============================================================================
// Kernel 3: output projection + bias + residual (fp32).
// ============================================================================
__global__ void __launch_bounds__(256) proj_kernel(
    const float* __restrict__ Wo, const float* __restrict__ bo,
    const float* __restrict__ hs, float* __restrict__ outp)
{
    __shared__ float a_s[32][132];
    __shared__ float b_s[32][68];

    const int tid = threadIdx.x;
    const int tx  = tid & 15;
    const int ty  = tid >> 4;
    const int m0  = blockIdx.y * 128;
    const int n0  = blockIdx.x * 64;

    const int arow = tid >> 1;
    const int acol = (tid & 1) * 16;
    const int brow = tid >> 3;
    const int bcol = (tid & 7) * 8;

    float acc[8][4];
#pragma unroll
    for (int i = 0; i < 8; i++)
#pragma unroll
        for (int j = 0; j < 4; j++) acc[i][j] = 0.f;

    for (int k0 = 0; k0 < D_MODEL; k0 += 32) {
        float4 av[4], bv[2];
        const float4* ga = reinterpret_cast<const float4*>(
            g_o + (size_t)(m0 + arow) * D_MODEL + k0 + acol);
        av[0] = ga[0]; av[1] = ga[1]; av[2] = ga[2]; av[3] = ga[3];
        const float4* gb = reinterpret_cast<const float4*>(
            Wo + (size_t)(k0 + brow) * D_MODEL + n0 + bcol);
        bv[0] = gb[0]; bv[1] = gb[1];

        __syncthreads();
#pragma unroll
        for (int u = 0; u < 4; u++) {
            a_s[acol + 4*u + 0][arow] = av[u].x;
            a_s[acol + 4*u + 1][arow] = av[u].y;
            a_s[acol + 4*u + 2][arow] = av[u].z;
            a_s[acol + 4*u + 3][arow] = av[u].w;
        }
        *reinterpret_cast<float4*>(&b_s[brow][bcol])     = bv[0];
        *reinterpret_cast<float4*>(&b_s[brow][bcol + 4]) = bv[1];
        __syncthreads();

#pragma unroll 8
        for (int kk = 0; kk < 32; kk++) {
            float4 a0 = *reinterpret_cast<const float4*>(&a_s[kk][ty * 8]);
            float4 a1 = *reinterpret_cast<const float4*>(&a_s[kk][ty * 8 + 4]);
            float4 b0 = *reinterpret_cast<const float4*>(&b_s[kk][tx * 4]);
            float ar[8] = {a0.x, a0.y, a0.z, a0.w, a1.x, a1.y, a1.z, a1.w};
            float br[4] = {b0.x, b0.y, b0.z, b0.w};
#pragma unroll
            for (int i = 0; i < 8; i++)
#pragma unroll
                for (int j = 0; j < 4; j++)
                    acc[i][j] = fmaf(ar[i], br[j], acc[i][j]);
        }
    }

    const int n = n0 + tx * 4;
    const float4 bb = *reinterpret_cast<const float4*>(bo + n);
#pragma unroll
    for (int i = 0; i < 8; i++) {
        const int m = m0 + ty * 8 + i;
        const float4 res = *reinterpret_cast<const float4*>(
            hs + (size_t)m * D_MODEL + n);
        *reinterpret_cast<float4*>(outp + (size_t)m * D_MODEL + n) =
            make_float4(acc[i][0] + bb.x + res.x,
                        acc[i][1] + bb.y + res.y,
                        acc[i][2] + bb.z + res.z,
                        acc[i][3] + bb.w + res.w);
    }
}

// ============================================================================
// Launch
// ============================================================================
extern "C" void kernel_launch(void* const* d_in, const int* in_sizes, int n_in,
                              void* d_out, int out_size)
{
    const float* hs        = (const float*)d_in[0];
    const float* p_out     = (const float*)d_in[1];
    const float* p_out_inv = (const float*)d_in[2];
    const float* Wq        = (const float*)d_in[3];
    const float* Wk        = (const float*)d_in[4];
    const float* Wv        = (const float*)d_in[5];
    const float* Wo        = (const float*)d_in[6];
    const float* bo        = (const float*)d_in[7];
    float* out             = (float*)d_out;

    qkv_kernel<<<dim3(8, 32, 3), 256>>>(hs, Wq, Wk, Wv, p_out, p_out_inv);
    attn_kernel<<<dim3(32, 8), 256>>>();
    proj_kernel<<<dim3(8, 32), 256>>>(Wo, bo, hs, out);
}

// round 9
// speedup vs baseline: 5.5110x; 1.7001x over previous
#include <cuda_runtime.h>
#include <cuda_bf16.h>
#include <cstdint>
#include <stdint.h>
#include <math.h>

// Problem constants (fixed by the reference):
//   B=1, T_OUT=8, L=512 -> S=4096 tokens, D=512, H=8 heads, hd=64
#define S_TOK   4096
#define D_MODEL 512
#define NH      8
#define HD      64

// Scratch (device globals: allocation-free, graph-safe).
__device__ __nv_bfloat16 g_qb[NH * S_TOK * HD];   // [h][s][hd], CAPE'd, pre-scaled
__device__ __nv_bfloat16 g_kb[NH * S_TOK * HD];   // [h][s][hd], CAPE'd
__device__ __nv_bfloat16 g_vb[NH * S_TOK * HD];   // [h][s][hd]
__device__ __nv_bfloat16 g_ob[S_TOK * D_MODEL];   // attention output, (S, D) bf16

// ----------------------------------------------------------------------------
// PTX helpers: ldmatrix + bf16 mma (fp32 accum)
// ----------------------------------------------------------------------------
__device__ __forceinline__ uint32_t smem_u32(const void* p) {
    return (uint32_t)__cvta_generic_to_shared(p);
}
__device__ __forceinline__ void ldsm_x4(uint32_t* r, uint32_t a) {
    asm volatile("ldmatrix.sync.aligned.m8n8.x4.shared.b16 {%0,%1,%2,%3}, [%4];"
                 : "=r"(r[0]), "=r"(r[1]), "=r"(r[2]), "=r"(r[3]) : "r"(a));
}
__device__ __forceinline__ void ldsm_x4_t(uint32_t* r, uint32_t a) {
    asm volatile("ldmatrix.sync.aligned.m8n8.x4.trans.shared.b16 {%0,%1,%2,%3}, [%4];"
                 : "=r"(r[0]), "=r"(r[1]), "=r"(r[2]), "=r"(r[3]) : "r"(a));
}
__device__ __forceinline__ void mma_bf16(float* c, const uint32_t* a,
                                         uint32_t b0, uint32_t b1) {
    asm volatile(
        "mma.sync.aligned.m16n8k16.row.col.f32.bf16.bf16.f32 "
        "{%0,%1,%2,%3}, {%4,%5,%6,%7}, {%8,%9}, {%0,%1,%2,%3};"
        : "+f"(c[0]), "+f"(c[1]), "+f"(c[2]), "+f"(c[3])
        : "r"(a[0]), "r"(a[1]), "r"(a[2]), "r"(a[3]), "r"(b0), "r"(b1));
}
__device__ __forceinline__ uint32_t pack_bf16x2(float a, float b) {
    __nv_bfloat162 t = __floats2bfloat162_rn(a, b);
    return *reinterpret_cast<uint32_t*>(&t);
}

// ============================================================================
// Kernel 1: QKV projection on tensor cores + CAPE epilogue -> bf16 q/k/v.
//   BM=128, BN=128, BK=64; 256 threads (8 warps, m16 x n128 per warp).
//   A (x fp32) and B (W fp32 [k][n]) converted to bf16 while staging to smem.
//   A frags: non-trans ldmatrix (Q pattern). B frags: trans ldmatrix (V pattern).
//   grid (4, 32, 3); blockIdx.z = q/k/v.
// ============================================================================
__global__ void __launch_bounds__(256) qkv_mma_kernel(
    const float* __restrict__ x,
    const float* __restrict__ Wq, const float* __restrict__ Wk,
    const float* __restrict__ Wv,
    const float* __restrict__ p_out, const float* __restrict__ p_out_inv)
{
    __shared__ __nv_bfloat16 a_s[128 * 64];   // [m][k] swizzled (8 chunks/row)
    __shared__ __nv_bfloat16 b_s[64 * 128];   // [k][n] swizzled (16 chunks/row)

    const int mode = blockIdx.z;   // 0=q, 1=k, 2=v
    const float* __restrict__ W  = (mode == 0) ? Wq : (mode == 1) ? Wk : Wv;
    __nv_bfloat16* __restrict__ out =
        (mode == 0) ? g_qb : (mode == 1) ? g_kb : g_vb;
    const float* __restrict__ Pm = (mode == 0) ? p_out_inv : p_out;

    const int tid  = threadIdx.x;
    const int lane = tid & 31;
    const int w    = tid >> 5;
    const int m0   = blockIdx.y * 128;
    const int n0   = blockIdx.x * 128;

    float cf[16][4];
#pragma unroll
    for (int nt = 0; nt < 16; nt++)
#pragma unroll
        for (int c = 0; c < 4; c++) cf[nt][c] = 0.f;

    for (int k0 = 0; k0 < D_MODEL; k0 += 64) {
        __syncthreads();
        // ---- stage A: 128x64 fp32 -> bf16, swizzled ----
#pragma unroll
        for (int u = 0; u < 4; u++) {
            const int gid = u * 256 + tid;      // 0..1023 8-elem chunks
            const int row = gid >> 3;
            const int c8  = gid & 7;
            const float4* src = reinterpret_cast<const float4*>(
                x + (size_t)(m0 + row) * D_MODEL + k0 + c8 * 8);
            const float4 f0 = src[0], f1 = src[1];
            uint4 d;
            d.x = pack_bf16x2(f0.x, f0.y); d.y = pack_bf16x2(f0.z, f0.w);
            d.z = pack_bf16x2(f1.x, f1.y); d.w = pack_bf16x2(f1.z, f1.w);
            *reinterpret_cast<uint4*>(a_s + row * 64 + ((c8 ^ (row & 7)) << 3)) = d;
        }
        // ---- stage B: 64x128 fp32 [k][n] -> bf16, swizzled ----
#pragma unroll
        for (int u = 0; u < 4; u++) {
            const int gid = u * 256 + tid;      // 0..1023 8-elem chunks
            const int row = gid >> 4;           // k row 0..63
            const int c16 = gid & 15;
            const float4* src = reinterpret_cast<const float4*>(
                W + (size_t)(k0 + row) * D_MODEL + n0 + c16 * 8);
            const float4 f0 = src[0], f1 = src[1];
            uint4 d;
            d.x = pack_bf16x2(f0.x, f0.y); d.y = pack_bf16x2(f0.z, f0.w);
            d.z = pack_bf16x2(f1.x, f1.y); d.w = pack_bf16x2(f1.z, f1.w);
            *reinterpret_cast<uint4*>(b_s + row * 128 + ((c16 ^ (row & 7)) << 3)) = d;
        }
        __syncthreads();

        // ---- A frags: m16 x k64 = 4 k-tiles ----
        uint32_t qa[4][4];
        {
            const int mi = lane >> 3, rr = lane & 7;
            const int arow = w * 16 + ((mi & 1) << 3) + rr;
#pragma unroll
            for (int kt = 0; kt < 4; kt++) {
                const int ch = (kt * 2 + (mi >> 1)) ^ (arow & 7);
                ldsm_x4(qa[kt], smem_u32(a_s + arow * 64 + ch * 8));
            }
        }
        // ---- B frags + mma: 16 n-tiles x 4 k-steps ----
        {
            const int j = lane >> 3, rr = lane & 7;
#pragma unroll
            for (int nt = 0; nt < 16; nt++) {
#pragma unroll
                for (int kt2 = 0; kt2 < 2; kt2++) {
                    const int brow = kt2 * 32 + j * 8 + rr;
                    const int ch = nt ^ (brow & 7);
                    uint32_t vb[4];
                    ldsm_x4_t(vb, smem_u32(b_s + brow * 128 + ch * 8));
                    mma_bf16(cf[nt], qa[kt2 * 2],     vb[0], vb[1]);
                    mma_bf16(cf[nt], qa[kt2 * 2 + 1], vb[2], vb[3]);
                }
            }
        }
    }

    // ---- CAPE epilogue (q,k): mix 4-col groups. Lanes (2q, 2q+1) of each
    //      quad-pair jointly hold cols [4j..4j+3]; exchange via shfl_xor(1). --
    if (mode < 2) {
        const float* P = Pm + (m0 >> 9) * 16;   // frame = m0/512, P row-major [k][g]
        float pm[16];
#pragma unroll
        for (int t = 0; t < 16; t++) pm[t] = P[t];
        const int gb = (lane & 1) * 2;          // own g-offset within 4-group
#pragma unroll
        for (int nt = 0; nt < 16; nt++) {
#pragma unroll
            for (int hf = 0; hf < 2; hf++) {
                const float v0 = cf[nt][hf * 2], v1 = cf[nt][hf * 2 + 1];
                const float p0 = __shfl_xor_sync(0xffffffffu, v0, 1);
                const float p1 = __shfl_xor_sync(0xffffffffu, v1, 1);
                const float a0 = (lane & 1) ? p0 : v0;
                const float a1 = (lane & 1) ? p1 : v1;
                const float a2 = (lane & 1) ? v0 : p0;
                const float a3 = (lane & 1) ? v1 : p1;
                cf[nt][hf * 2]     = a0 * pm[gb]     + a1 * pm[4 + gb]
                                   + a2 * pm[8 + gb] + a3 * pm[12 + gb];
                cf[nt][hf * 2 + 1] = a0 * pm[gb + 1]     + a1 * pm[4 + gb + 1]
                                   + a2 * pm[8 + gb + 1] + a3 * pm[12 + gb + 1];
            }
        }
    }
    if (mode == 0) {   // fold softmax scale hd^-0.5 = 0.125 into q
#pragma unroll
        for (int nt = 0; nt < 16; nt++)
#pragma unroll
            for (int c = 0; c < 4; c++) cf[nt][c] *= 0.125f;
    }

    // ---- store bf16 into per-head layout [h][s][hd] ----
    const int row0 = m0 + w * 16 + (lane >> 2);
    const int row1 = row0 + 8;
#pragma unroll
    for (int nt = 0; nt < 16; nt++) {
        const int ng = n0 + nt * 8 + (lane & 3) * 2;
        const int h  = ng >> 6;
        const int c  = ng & 63;
        *reinterpret_cast<uint32_t*>(out + ((size_t)h * S_TOK + row0) * HD + c) =
            pack_bf16x2(cf[nt][0], cf[nt][1]);
        *reinterpret_cast<uint32_t*>(out + ((size_t)h * S_TOK + row1) * HD + c) =
            pack_bf16x2(cf[nt][2], cf[nt][3]);
    }
}

// ============================================================================
// Kernel 2: flash attention, bf16 tensor-core (unchanged mainloop; bf16 out).
// ============================================================================
__global__ void __launch_bounds__(256, 1) attn_kernel()
{
    __shared__ __nv_bfloat16 q_s[128 * 64];
    __shared__ __nv_bfloat16 k_s[128 * 64];
    __shared__ __nv_bfloat16 v_s[128 * 64];

    const int tid  = threadIdx.x;
    const int lane = tid & 31;
    const int w    = tid >> 5;
    const int h    = blockIdx.y;
    const int m0   = blockIdx.x * 128;

    const __nv_bfloat16* __restrict__ qg = g_qb + (size_t)h * S_TOK * HD;
    const __nv_bfloat16* __restrict__ kg = g_kb + (size_t)h * S_TOK * HD;
    const __nv_bfloat16* __restrict__ vg = g_vb + (size_t)h * S_TOK * HD;

#pragma unroll
    for (int u = 0; u < 4; u++) {
        const int gid = u * 256 + tid;
        const int row = gid >> 3;
        const int c8  = gid & 7;
        uint4 d = *reinterpret_cast<const uint4*>(
            qg + (size_t)(m0 + row) * HD + c8 * 8);
        *reinterpret_cast<uint4*>(q_s + row * 64 + ((c8 ^ (row & 7)) << 3)) = d;
    }
    __syncthreads();

    uint32_t qa[4][4];
    {
        const int mi = lane >> 3, rr = lane & 7;
        const int row = w * 16 + ((mi & 1) << 3) + rr;
#pragma unroll
        for (int kt = 0; kt < 4; kt++) {
            const int ch = (kt * 2 + (mi >> 1)) ^ (row & 7);
            ldsm_x4(qa[kt], smem_u32(q_s + row * 64 + ch * 8));
        }
    }

    float m_i0 = -1e30f, m_i1 = -1e30f, l0 = 0.f, l1 = 0.f;
    float of[8][4];
#pragma unroll
    for (int nt = 0; nt < 8; nt++)
#pragma unroll
        for (int c = 0; c < 4; c++) of[nt][c] = 0.f;

    for (int it = 0; it < S_TOK / 128; it++) {
        __syncthreads();
        {
            const __nv_bfloat16* ks = kg + (size_t)(it * 128) * HD;
            const __nv_bfloat16* vs = vg + (size_t)(it * 128) * HD;
#pragma unroll
            for (int u = 0; u < 4; u++) {
                const int gid = u * 256 + tid;
                const int row = gid >> 3;
                const int c8  = gid & 7;
                const int so  = row * 64 + ((c8 ^ (row & 7)) << 3);
                uint4 dk = *reinterpret_cast<const uint4*>(ks + row * 64 + c8 * 8);
                uint4 dv = *reinterpret_cast<const uint4*>(vs + row * 64 + c8 * 8);
                *reinterpret_cast<uint4*>(k_s + so) = dk;
                *reinterpret_cast<uint4*>(v_s + so) = dv;
            }
        }
        __syncthreads();

        float sf[16][4];
#pragma unroll
        for (int nt = 0; nt < 16; nt++)
#pragma unroll
            for (int c = 0; c < 4; c++) sf[nt][c] = 0.f;

        {
            const int j = lane >> 3, rr = lane & 7;
#pragma unroll
            for (int nt = 0; nt < 16; nt++) {
                const int srow = nt * 8 + rr;
                uint32_t b[8];
                const int ch0 = (j)     ^ (srow & 7);
                const int ch1 = (4 + j) ^ (srow & 7);
                ldsm_x4(b,     smem_u32(k_s + srow * 64 + ch0 * 8));
                ldsm_x4(b + 4, smem_u32(k_s + srow * 64 + ch1 * 8));
                mma_bf16(sf[nt], qa[0], b[0], b[1]);
                mma_bf16(sf[nt], qa[1], b[2], b[3]);
                mma_bf16(sf[nt], qa[2], b[4], b[5]);
                mma_bf16(sf[nt], qa[3], b[6], b[7]);
            }
        }

        float mx0 = sf[0][0], mx1 = sf[0][2];
#pragma unroll
        for (int nt = 0; nt < 16; nt++) {
            mx0 = fmaxf(mx0, fmaxf(sf[nt][0], sf[nt][1]));
            mx1 = fmaxf(mx1, fmaxf(sf[nt][2], sf[nt][3]));
        }
        mx0 = fmaxf(mx0, __shfl_xor_sync(0xffffffffu, mx0, 1));
        mx0 = fmaxf(mx0, __shfl_xor_sync(0xffffffffu, mx0, 2));
        mx1 = fmaxf(mx1, __shfl_xor_sync(0xffffffffu, mx1, 1));
        mx1 = fmaxf(mx1, __shfl_xor_sync(0xffffffffu, mx1, 2));

        const float mn0 = fmaxf(m_i0, mx0);
        const float mn1 = fmaxf(m_i1, mx1);
        const float al0 = __expf(m_i0 - mn0);
        const float al1 = __expf(m_i1 - mn1);
        m_i0 = mn0; m_i1 = mn1;

        float rs0 = 0.f, rs1 = 0.f;
        uint32_t pa[8][4];
#pragma unroll
        for (int nt = 0; nt < 16; nt++) {
            const float e0 = __expf(sf[nt][0] - mn0);
            const float e1 = __expf(sf[nt][1] - mn0);
            const float e2 = __expf(sf[nt][2] - mn1);
            const float e3 = __expf(sf[nt][3] - mn1);
            rs0 += e0 + e1; rs1 += e2 + e3;
            const uint32_t p01 = pack_bf16x2(e0, e1);
            const uint32_t p23 = pack_bf16x2(e2, e3);
            const int jt = nt >> 1;
            if ((nt & 1) == 0) { pa[jt][0] = p01; pa[jt][1] = p23; }
            else               { pa[jt][2] = p01; pa[jt][3] = p23; }
        }
        rs0 += __shfl_xor_sync(0xffffffffu, rs0, 1);
        rs0 += __shfl_xor_sync(0xffffffffu, rs0, 2);
        rs1 += __shfl_xor_sync(0xffffffffu, rs1, 1);
        rs1 += __shfl_xor_sync(0xffffffffu, rs1, 2);
        l0 = l0 * al0 + rs0;
        l1 = l1 * al1 + rs1;

#pragma unroll
        for (int nt = 0; nt < 8; nt++) {
            of[nt][0] *= al0; of[nt][1] *= al0;
            of[nt][2] *= al1; of[nt][3] *= al1;
        }

        {
            const int j = lane >> 3, rr = lane & 7;
#pragma unroll
            for (int kt2 = 0; kt2 < 4; kt2++) {
                const int vrow = kt2 * 32 + j * 8 + rr;
#pragma unroll
                for (int nt = 0; nt < 8; nt++) {
                    uint32_t vb[4];
                    const int ch = nt ^ (vrow & 7);
                    ldsm_x4_t(vb, smem_u32(v_s + vrow * 64 + ch * 8));
                    mma_bf16(of[nt], pa[2 * kt2],     vb[0], vb[1]);
                    mma_bf16(of[nt], pa[2 * kt2 + 1], vb[2], vb[3]);
                }
            }
        }
    }

    // ---- normalize + store bf16 to (S, D) layout ----
    const float inv0 = 1.0f / l0;
    const float inv1 = 1.0f / l1;
    const int row0 = m0 + w * 16 + (lane >> 2);
    const int row1 = row0 + 8;
    const int cbase = h * HD + (lane & 3) * 2;
#pragma unroll
    for (int nt = 0; nt < 8; nt++) {
        const int col = cbase + nt * 8;
        *reinterpret_cast<uint32_t*>(g_ob + (size_t)row0 * D_MODEL + col) =
            pack_bf16x2(of[nt][0] * inv0, of[nt][1] * inv0);
        *reinterpret_cast<uint32_t*>(g_ob + (size_t)row1 * D_MODEL + col) =
            pack_bf16x2(of[nt][2] * inv1, of[nt][3] * inv1);
    }
}

// ============================================================================
// Kernel 3: output projection on tensor cores + bias + residual (fp32 out).
//   A = g_ob bf16 [S][512] (direct copy to smem); B = Wo fp32 (converted).
//   grid (4, 32), block 256.
// ============================================================================
__global__ void __launch_bounds__(256) proj_mma_kernel(
    const float* __restrict__ Wo, const float* __restrict__ bo,
    const float* __restrict__ hs, float* __restrict__ outp)
{
    __shared__ __nv_bfloat16 a_s[128 * 64];
    __shared__ __nv_bfloat16 b_s[64 * 128];

    const int tid  = threadIdx.x;
    const int lane = tid & 31;
    const int w    = tid >> 5;
    const int m0   = blockIdx.y * 128;
    const int n0   = blockIdx.x * 128;

    float cf[16][4];
#pragma unroll
    for (int nt = 0; nt < 16; nt++)
#pragma unroll
        for (int c = 0; c < 4; c++) cf[nt][c] = 0.f;

    for (int k0 = 0; k0 < D_MODEL; k0 += 64) {
        __syncthreads();
        // ---- stage A: 128x64 bf16, direct 16B copy, swizzled ----
#pragma unroll
        for (int u = 0; u < 4; u++) {
            const int gid = u * 256 + tid;
            const int row = gid >> 3;
            const int c8  = gid & 7;
            uint4 d = *reinterpret_cast<const uint4*>(
                g_ob + (size_t)(m0 + row) * D_MODEL + k0 + c8 * 8);
            *reinterpret_cast<uint4*>(a_s + row * 64 + ((c8 ^ (row & 7)) << 3)) = d;
        }
        // ---- stage B: 64x128 fp32 -> bf16, swizzled ----
#pragma unroll
        for (int u = 0; u < 4; u++) {
            const int gid = u * 256 + tid;
            const int row = gid >> 4;
            const int c16 = gid & 15;
            const float4* src = reinterpret_cast<const float4*>(
                Wo + (size_t)(k0 + row) * D_MODEL + n0 + c16 * 8);
            const float4 f0 = src[0], f1 = src[1];
            uint4 d;
            d.x = pack_bf16x2(f0.x, f0.y); d.y = pack_bf16x2(f0.z, f0.w);
            d.z = pack_bf16x2(f1.x, f1.y); d.w = pack_bf16x2(f1.z, f1.w);
            *reinterpret_cast<uint4*>(b_s + row * 128 + ((c16 ^ (row & 7)) << 3)) = d;
        }
        __syncthreads();

        uint32_t qa[4][4];
        {
            const int mi = lane >> 3, rr = lane & 7;
            const int arow = w * 16 + ((mi & 1) << 3) + rr;
#pragma unroll
            for (int kt = 0; kt < 4; kt++) {
                const int ch = (kt * 2 + (mi >> 1)) ^ (arow & 7);
                ldsm_x4(qa[kt], smem_u32(a_s + arow * 64 + ch * 8));
            }
        }
        {
            const int j = lane >> 3, rr = lane & 7;
#pragma unroll
            for (int nt = 0; nt < 16; nt++) {
#pragma unroll
                for (int kt2 = 0; kt2 < 2; kt2++) {
                    const int brow = kt2 * 32 + j * 8 + rr;
                    const int ch = nt ^ (brow & 7);
                    uint32_t vb[4];
                    ldsm_x4_t(vb, smem_u32(b_s + brow * 128 + ch * 8));
                    mma_bf16(cf[nt], qa[kt2 * 2],     vb[0], vb[1]);
                    mma_bf16(cf[nt], qa[kt2 * 2 + 1], vb[2], vb[3]);
                }
            }
        }
    }

    // ---- epilogue: + bias + residual, fp32 out ----
    const int row0 = m0 + w * 16 + (lane >> 2);
    const int row1 = row0 + 8;
#pragma unroll
    for (int nt = 0; nt < 16; nt++) {
        const int col = n0 + nt * 8 + (lane & 3) * 2;
        const float2 bb = *reinterpret_cast<const float2*>(bo + col);
        const float2 r0 = *reinterpret_cast<const float2*>(
            hs + (size_t)row0 * D_MODEL + col);
        const float2 r1 = *reinterpret_cast<const float2*>(
            hs + (size_t)row1 * D_MODEL + col);
        *reinterpret_cast<float2*>(outp + (size_t)row0 * D_MODEL + col) =
            make_float2(cf[nt][0] + bb.x + r0.x, cf[nt][1] + bb.y + r0.y);
        *reinterpret_cast<float2*>(outp + (size_t)row1 * D_MODEL + col) =
            make_float2(cf[nt][2] + bb.x + r1.x, cf[nt][3] + bb.y + r1.y);
    }
}

// ============================================================================
// Launch
// ============================================================================
extern "C" void kernel_launch(void* const* d_in, const int* in_sizes, int n_in,
                              void* d_out, int out_size)
{
    const float* hs        = (const float*)d_in[0];
    const float* p_out     = (const float*)d_in[1];
    const float* p_out_inv = (const float*)d_in[2];
    const float* Wq        = (const float*)d_in[3];
    const float* Wk        = (const float*)d_in[4];
    const float* Wv        = (const float*)d_in[5];
    const float* Wo        = (const float*)d_in[6];
    const float* bo        = (const float*)d_in[7];
    float* out             = (float*)d_out;

    qkv_mma_kernel<<<dim3(4, 32, 3), 256>>>(hs, Wq, Wk, Wv, p_out, p_out_inv);
    attn_kernel<<<dim3(32, 8), 256>>>();
    proj_mma_kernel<<<dim3(4, 32), 256>>>(Wo, bo, hs, out);
}

// round 10
// speedup vs baseline: 5.8431x; 1.0603x over previous
#include <cuda_runtime.h>
#include <cuda_bf16.h>
#include <cstdint>
#include <stdint.h>
#include <math.h>

// Problem constants (fixed by the reference):
//   B=1, T_OUT=8, L=512 -> S=4096 tokens, D=512, H=8 heads, hd=64
#define S_TOK   4096
#define D_MODEL 512
#define NH      8
#define HD      64

// Scratch (device globals: allocation-free, graph-safe).
__device__ __nv_bfloat16 g_qb[NH * S_TOK * HD];   // [h][s][hd], CAPE'd, scaled
__device__ __nv_bfloat16 g_kb[NH * S_TOK * HD];   // [h][s][hd], CAPE'd
__device__ __nv_bfloat16 g_vb[NH * S_TOK * HD];   // [h][s][hd]
__device__ __nv_bfloat16 g_ob[S_TOK * D_MODEL];   // attention output, (S, D) bf16

// ----------------------------------------------------------------------------
// PTX helpers: ldmatrix + bf16 mma (fp32 accum)
// ----------------------------------------------------------------------------
__device__ __forceinline__ uint32_t smem_u32(const void* p) {
    return (uint32_t)__cvta_generic_to_shared(p);
}
__device__ __forceinline__ void ldsm_x4(uint32_t* r, uint32_t a) {
    asm volatile("ldmatrix.sync.aligned.m8n8.x4.shared.b16 {%0,%1,%2,%3}, [%4];"
                 : "=r"(r[0]), "=r"(r[1]), "=r"(r[2]), "=r"(r[3]) : "r"(a));
}
__device__ __forceinline__ void ldsm_x4_t(uint32_t* r, uint32_t a) {
    asm volatile("ldmatrix.sync.aligned.m8n8.x4.trans.shared.b16 {%0,%1,%2,%3}, [%4];"
                 : "=r"(r[0]), "=r"(r[1]), "=r"(r[2]), "=r"(r[3]) : "r"(a));
}
__device__ __forceinline__ void mma_bf16(float* c, const uint32_t* a,
                                         uint32_t b0, uint32_t b1) {
    asm volatile(
        "mma.sync.aligned.m16n8k16.row.col.f32.bf16.bf16.f32 "
        "{%0,%1,%2,%3}, {%4,%5,%6,%7}, {%8,%9}, {%0,%1,%2,%3};"
        : "+f"(c[0]), "+f"(c[1]), "+f"(c[2]), "+f"(c[3])
        : "r"(a[0]), "r"(a[1]), "r"(a[2]), "r"(a[3]), "r"(b0), "r"(b1));
}
__device__ __forceinline__ uint32_t pack_bf16x2(float a, float b) {
    __nv_bfloat162 t = __floats2bfloat162_rn(a, b);
    return *reinterpret_cast<uint32_t*>(&t);
}

// ============================================================================
// Kernel 1: QKV projection on tensor cores + CAPE epilogue -> bf16 q/k/v.
//   BM=128, BN=64, BK=64; 256 threads; 2 CTAs/SM (cf[8][4] = low regs).
//   grid (8, 32, 3); blockIdx.z = q/k/v.
// ============================================================================
__global__ void __launch_bounds__(256, 2) qkv_mma_kernel(
    const float* __restrict__ x,
    const float* __restrict__ Wq, const float* __restrict__ Wk,
    const float* __restrict__ Wv,
    const float* __restrict__ p_out, const float* __restrict__ p_out_inv)
{
    __shared__ __nv_bfloat16 a_s[128 * 64];   // [m][k] swizzled (8 chunks/row)
    __shared__ __nv_bfloat16 b_s[64 * 64];    // [k][n] swizzled (8 chunks/row)

    const int mode = blockIdx.z;   // 0=q, 1=k, 2=v
    const float* __restrict__ W  = (mode == 0) ? Wq : (mode == 1) ? Wk : Wv;
    __nv_bfloat16* __restrict__ out =
        (mode == 0) ? g_qb : (mode == 1) ? g_kb : g_vb;
    const float* __restrict__ Pm = (mode == 0) ? p_out_inv : p_out;

    const int tid  = threadIdx.x;
    const int lane = tid & 31;
    const int w    = tid >> 5;
    const int m0   = blockIdx.y * 128;
    const int n0   = blockIdx.x * 64;

    float cf[8][4];
#pragma unroll
    for (int nt = 0; nt < 8; nt++)
#pragma unroll
        for (int c = 0; c < 4; c++) cf[nt][c] = 0.f;

    for (int k0 = 0; k0 < D_MODEL; k0 += 64) {
        __syncthreads();
        // ---- stage A: 128x64 fp32 -> bf16, swizzled ----
#pragma unroll
        for (int u = 0; u < 4; u++) {
            const int gid = u * 256 + tid;      // 0..1023 8-elem chunks
            const int row = gid >> 3;
            const int c8  = gid & 7;
            const float4* src = reinterpret_cast<const float4*>(
                x + (size_t)(m0 + row) * D_MODEL + k0 + c8 * 8);
            const float4 f0 = src[0], f1 = src[1];
            uint4 d;
            d.x = pack_bf16x2(f0.x, f0.y); d.y = pack_bf16x2(f0.z, f0.w);
            d.z = pack_bf16x2(f1.x, f1.y); d.w = pack_bf16x2(f1.z, f1.w);
            *reinterpret_cast<uint4*>(a_s + row * 64 + ((c8 ^ (row & 7)) << 3)) = d;
        }
        // ---- stage B: 64x64 fp32 [k][n] -> bf16, swizzled ----
#pragma unroll
        for (int u = 0; u < 2; u++) {
            const int gid = u * 256 + tid;      // 0..511 8-elem chunks
            const int row = gid >> 3;           // k row 0..63
            const int c8  = gid & 7;
            const float4* src = reinterpret_cast<const float4*>(
                W + (size_t)(k0 + row) * D_MODEL + n0 + c8 * 8);
            const float4 f0 = src[0], f1 = src[1];
            uint4 d;
            d.x = pack_bf16x2(f0.x, f0.y); d.y = pack_bf16x2(f0.z, f0.w);
            d.z = pack_bf16x2(f1.x, f1.y); d.w = pack_bf16x2(f1.z, f1.w);
            *reinterpret_cast<uint4*>(b_s + row * 64 + ((c8 ^ (row & 7)) << 3)) = d;
        }
        __syncthreads();

        // ---- A frags: m16 x k64 = 4 k-tiles ----
        uint32_t qa[4][4];
        {
            const int mi = lane >> 3, rr = lane & 7;
            const int arow = w * 16 + ((mi & 1) << 3) + rr;
#pragma unroll
            for (int kt = 0; kt < 4; kt++) {
                const int ch = (kt * 2 + (mi >> 1)) ^ (arow & 7);
                ldsm_x4(qa[kt], smem_u32(a_s + arow * 64 + ch * 8));
            }
        }
        // ---- B frags + mma: 8 n-tiles x 4 k-steps ----
        {
            const int j = lane >> 3, rr = lane & 7;
#pragma unroll
            for (int nt = 0; nt < 8; nt++) {
#pragma unroll
                for (int kt2 = 0; kt2 < 2; kt2++) {
                    const int brow = kt2 * 32 + j * 8 + rr;
                    const int ch = nt ^ (brow & 7);
                    uint32_t vb[4];
                    ldsm_x4_t(vb, smem_u32(b_s + brow * 64 + ch * 8));
                    mma_bf16(cf[nt], qa[kt2 * 2],     vb[0], vb[1]);
                    mma_bf16(cf[nt], qa[kt2 * 2 + 1], vb[2], vb[3]);
                }
            }
        }
    }

    // ---- CAPE epilogue (q,k): mix 4-col groups via shfl_xor(1). ----
    if (mode < 2) {
        const float* P = Pm + (m0 >> 9) * 16;   // frame = m0/512, P row-major [k][g]
        float pm[16];
#pragma unroll
        for (int t = 0; t < 16; t++) pm[t] = P[t];
        const int gb = (lane & 1) * 2;
#pragma unroll
        for (int nt = 0; nt < 8; nt++) {
#pragma unroll
            for (int hf = 0; hf < 2; hf++) {
                const float v0 = cf[nt][hf * 2], v1 = cf[nt][hf * 2 + 1];
                const float p0 = __shfl_xor_sync(0xffffffffu, v0, 1);
                const float p1 = __shfl_xor_sync(0xffffffffu, v1, 1);
                const float a0 = (lane & 1) ? p0 : v0;
                const float a1 = (lane & 1) ? p1 : v1;
                const float a2 = (lane & 1) ? v0 : p0;
                const float a3 = (lane & 1) ? v1 : p1;
                cf[nt][hf * 2]     = a0 * pm[gb]     + a1 * pm[4 + gb]
                                   + a2 * pm[8 + gb] + a3 * pm[12 + gb];
                cf[nt][hf * 2 + 1] = a0 * pm[gb + 1]     + a1 * pm[4 + gb + 1]
                                   + a2 * pm[8 + gb + 1] + a3 * pm[12 + gb + 1];
            }
        }
    }
    if (mode == 0) {   // fold softmax scale AND log2(e) into q: 0.125 * 1.4426950
#pragma unroll
        for (int nt = 0; nt < 8; nt++)
#pragma unroll
            for (int c = 0; c < 4; c++) cf[nt][c] *= 0.18033688f;
    }

    // ---- store bf16 into per-head layout [h][s][hd] ----
    const int row0 = m0 + w * 16 + (lane >> 2);
    const int row1 = row0 + 8;
#pragma unroll
    for (int nt = 0; nt < 8; nt++) {
        const int ng = n0 + nt * 8 + (lane & 3) * 2;
        const int h  = ng >> 6;
        const int c  = ng & 63;
        *reinterpret_cast<uint32_t*>(out + ((size_t)h * S_TOK + row0) * HD + c) =
            pack_bf16x2(cf[nt][0], cf[nt][1]);
        *reinterpret_cast<uint32_t*>(out + ((size_t)h * S_TOK + row1) * HD + c) =
            pack_bf16x2(cf[nt][2], cf[nt][3]);
    }
}

// ============================================================================
// Kernel 2: flash attention, bf16 mma. Br=64, Bc=128, 4 warps, 2 CTAs/SM.
//   Per-warp fragment code identical to the validated 8-warp version.
//   Scores arrive pre-scaled by log2(e) -> exp2f softmax (single MUFU).
//   grid (64, 8), block 128. smem 40KB static.
// ============================================================================
__global__ void __launch_bounds__(128, 2) attn_kernel()
{
    __shared__ __nv_bfloat16 q_s[64 * 64];
    __shared__ __nv_bfloat16 k_s[128 * 64];
    __shared__ __nv_bfloat16 v_s[128 * 64];

    const int tid  = threadIdx.x;
    const int lane = tid & 31;
    const int w    = tid >> 5;          // warp 0..3 -> rows w*16..w*16+15
    const int h    = blockIdx.y;
    const int m0   = blockIdx.x * 64;

    const __nv_bfloat16* __restrict__ qg = g_qb + (size_t)h * S_TOK * HD;
    const __nv_bfloat16* __restrict__ kg = g_kb + (size_t)h * S_TOK * HD;
    const __nv_bfloat16* __restrict__ vg = g_vb + (size_t)h * S_TOK * HD;

    // ---- load Q tile (64 rows, swizzled) ----
#pragma unroll
    for (int u = 0; u < 4; u++) {
        const int gid = u * 128 + tid;          // 0..511 chunks
        const int row = gid >> 3;
        const int c8  = gid & 7;
        uint4 d = *reinterpret_cast<const uint4*>(
            qg + (size_t)(m0 + row) * HD + c8 * 8);
        *reinterpret_cast<uint4*>(q_s + row * 64 + ((c8 ^ (row & 7)) << 3)) = d;
    }
    __syncthreads();

    // ---- Q A-fragments: m16 x k64 = 4 k-tiles, register resident ----
    uint32_t qa[4][4];
    {
        const int mi = lane >> 3, rr = lane & 7;
        const int row = w * 16 + ((mi & 1) << 3) + rr;
#pragma unroll
        for (int kt = 0; kt < 4; kt++) {
            const int ch = (kt * 2 + (mi >> 1)) ^ (row & 7);
            ldsm_x4(qa[kt], smem_u32(q_s + row * 64 + ch * 8));
        }
    }

    float m_i0 = -1e30f, m_i1 = -1e30f, l0 = 0.f, l1 = 0.f;
    float of[8][4];
#pragma unroll
    for (int nt = 0; nt < 8; nt++)
#pragma unroll
        for (int c = 0; c < 4; c++) of[nt][c] = 0.f;

    for (int it = 0; it < S_TOK / 128; it++) {
        __syncthreads();  // all warps done with previous k_s/v_s
        {
            const __nv_bfloat16* ks = kg + (size_t)(it * 128) * HD;
            const __nv_bfloat16* vs = vg + (size_t)(it * 128) * HD;
#pragma unroll
            for (int u = 0; u < 8; u++) {
                const int gid = u * 128 + tid;  // 0..1023 chunks
                const int row = gid >> 3;
                const int c8  = gid & 7;
                const int so  = row * 64 + ((c8 ^ (row & 7)) << 3);
                uint4 dk = *reinterpret_cast<const uint4*>(ks + row * 64 + c8 * 8);
                uint4 dv = *reinterpret_cast<const uint4*>(vs + row * 64 + c8 * 8);
                *reinterpret_cast<uint4*>(k_s + so) = dk;
                *reinterpret_cast<uint4*>(v_s + so) = dv;
            }
        }
        __syncthreads();

        // ---- S = Q K^T : 16 n-tiles x 4 k-steps (non-trans K frags) ----
        float sf[16][4];
#pragma unroll
        for (int nt = 0; nt < 16; nt++)
#pragma unroll
            for (int c = 0; c < 4; c++) sf[nt][c] = 0.f;

        {
            const int j = lane >> 3, rr = lane & 7;
#pragma unroll
            for (int nt = 0; nt < 16; nt++) {
                const int srow = nt * 8 + rr;
                uint32_t b[8];
                const int ch0 = (j)     ^ (srow & 7);
                const int ch1 = (4 + j) ^ (srow & 7);
                ldsm_x4(b,     smem_u32(k_s + srow * 64 + ch0 * 8));
                ldsm_x4(b + 4, smem_u32(k_s + srow * 64 + ch1 * 8));
                mma_bf16(sf[nt], qa[0], b[0], b[1]);
                mma_bf16(sf[nt], qa[1], b[2], b[3]);
                mma_bf16(sf[nt], qa[2], b[4], b[5]);
                mma_bf16(sf[nt], qa[3], b[6], b[7]);
            }
        }

        // ---- online softmax in exp2 domain (scores pre-scaled by log2 e) ----
        float mx0 = sf[0][0], mx1 = sf[0][2];
#pragma unroll
        for (int nt = 0; nt < 16; nt++) {
            mx0 = fmaxf(mx0, fmaxf(sf[nt][0], sf[nt][1]));
            mx1 = fmaxf(mx1, fmaxf(sf[nt][2], sf[nt][3]));
        }
        mx0 = fmaxf(mx0, __shfl_xor_sync(0xffffffffu, mx0, 1));
        mx0 = fmaxf(mx0, __shfl_xor_sync(0xffffffffu, mx0, 2));
        mx1 = fmaxf(mx1, __shfl_xor_sync(0xffffffffu, mx1, 1));
        mx1 = fmaxf(mx1, __shfl_xor_sync(0xffffffffu, mx1, 2));

        const float mn0 = fmaxf(m_i0, mx0);
        const float mn1 = fmaxf(m_i1, mx1);
        const float al0 = exp2f(m_i0 - mn0);
        const float al1 = exp2f(m_i1 - mn1);
        m_i0 = mn0; m_i1 = mn1;

        float rs0 = 0.f, rs1 = 0.f;
        uint32_t pa[8][4];   // P A-frags for PV (k = 128 -> 8 k-tiles)
#pragma unroll
        for (int nt = 0; nt < 16; nt++) {
            const float e0 = exp2f(sf[nt][0] - mn0);
            const float e1 = exp2f(sf[nt][1] - mn0);
            const float e2 = exp2f(sf[nt][2] - mn1);
            const float e3 = exp2f(sf[nt][3] - mn1);
            rs0 += e0 + e1; rs1 += e2 + e3;
            const uint32_t p01 = pack_bf16x2(e0, e1);
            const uint32_t p23 = pack_bf16x2(e2, e3);
            const int jt = nt >> 1;
            if ((nt & 1) == 0) { pa[jt][0] = p01; pa[jt][1] = p23; }
            else               { pa[jt][2] = p01; pa[jt][3] = p23; }
        }
        rs0 += __shfl_xor_sync(0xffffffffu, rs0, 1);
        rs0 += __shfl_xor_sync(0xffffffffu, rs0, 2);
        rs1 += __shfl_xor_sync(0xffffffffu, rs1, 1);
        rs1 += __shfl_xor_sync(0xffffffffu, rs1, 2);
        l0 = l0 * al0 + rs0;
        l1 = l1 * al1 + rs1;

#pragma unroll
        for (int nt = 0; nt < 8; nt++) {
            of[nt][0] *= al0; of[nt][1] *= al0;
            of[nt][2] *= al1; of[nt][3] *= al1;
        }

        // ---- O += P V : trans V frags ----
        {
            const int j = lane >> 3, rr = lane & 7;
#pragma unroll
            for (int kt2 = 0; kt2 < 4; kt2++) {
                const int vrow = kt2 * 32 + j * 8 + rr;
#pragma unroll
                for (int nt = 0; nt < 8; nt++) {
                    uint32_t vb[4];
                    const int ch = nt ^ (vrow & 7);
                    ldsm_x4_t(vb, smem_u32(v_s + vrow * 64 + ch * 8));
                    mma_bf16(of[nt], pa[2 * kt2],     vb[0], vb[1]);
                    mma_bf16(of[nt], pa[2 * kt2 + 1], vb[2], vb[3]);
                }
            }
        }
    }

    // ---- normalize + store bf16 to (S, D) layout ----
    const float inv0 = 1.0f / l0;
    const float inv1 = 1.0f / l1;
    const int row0 = m0 + w * 16 + (lane >> 2);
    const int row1 = row0 + 8;
    const int cbase = h * HD + (lane & 3) * 2;
#pragma unroll
    for (int nt = 0; nt < 8; nt++) {
        const int col = cbase + nt * 8;
        *reinterpret_cast<uint32_t*>(g_ob + (size_t)row0 * D_MODEL + col) =
            pack_bf16x2(of[nt][0] * inv0, of[nt][1] * inv0);
        *reinterpret_cast<uint32_t*>(g_ob + (size_t)row1 * D_MODEL + col) =
            pack_bf16x2(of[nt][2] * inv1, of[nt][3] * inv1);
    }
}

// ============================================================================
// Kernel 3: output projection on tensor cores + bias + residual (fp32 out).
//   Unchanged from the 254.5us version. grid (4, 32), block 256.
// ============================================================================
__global__ void __launch_bounds__(256) proj_mma_kernel(
    const float* __restrict__ Wo, const float* __restrict__ bo,
    const float* __restrict__ hs, float* __restrict__ outp)
{
    __shared__ __nv_bfloat16 a_s[128 * 64];
    __shared__ __nv_bfloat16 b_s[64 * 128];

    const int tid  = threadIdx.x;
    const int lane = tid & 31;
    const int w    = tid >> 5;
    const int m0   = blockIdx.y * 128;
    const int n0   = blockIdx.x * 128;

    float cf[16][4];
#pragma unroll
    for (int nt = 0; nt < 16; nt++)
#pragma unroll
        for (int c = 0; c < 4; c++) cf[nt][c] = 0.f;

    for (int k0 = 0; k0 < D_MODEL; k0 += 64) {
        __syncthreads();
        // ---- stage A: 128x64 bf16, direct 16B copy, swizzled ----
#pragma unroll
        for (int u = 0; u < 4; u++) {
            const int gid = u * 256 + tid;
            const int row = gid >> 3;
            const int c8  = gid & 7;
            uint4 d = *reinterpret_cast<const uint4*>(
                g_ob + (size_t)(m0 + row) * D_MODEL + k0 + c8 * 8);
            *reinterpret_cast<uint4*>(a_s + row * 64 + ((c8 ^ (row & 7)) << 3)) = d;
        }
        // ---- stage B: 64x128 fp32 -> bf16, swizzled ----
#pragma unroll
        for (int u = 0; u < 4; u++) {
            const int gid = u * 256 + tid;
            const int row = gid >> 4;
            const int c16 = gid & 15;
            const float4* src = reinterpret_cast<const float4*>(
                Wo + (size_t)(k0 + row) * D_MODEL + n0 + c16 * 8);
            const float4 f0 = src[0], f1 = src[1];
            uint4 d;
            d.x = pack_bf16x2(f0.x, f0.y); d.y = pack_bf16x2(f0.z, f0.w);
            d.z = pack_bf16x2(f1.x, f1.y); d.w = pack_bf16x2(f1.z, f1.w);
            *reinterpret_cast<uint4*>(b_s + row * 128 + ((c16 ^ (row & 7)) << 3)) = d;
        }
        __syncthreads();

        uint32_t qa[4][4];
        {
            const int mi = lane >> 3, rr = lane & 7;
            const int arow = w * 16 + ((mi & 1) << 3) + rr;
#pragma unroll
            for (int kt = 0; kt < 4; kt++) {
                const int ch = (kt * 2 + (mi >> 1)) ^ (arow & 7);
                ldsm_x4(qa[kt], smem_u32(a_s + arow * 64 + ch * 8));
            }
        }
        {
            const int j = lane >> 3, rr = lane & 7;
#pragma unroll
            for (int nt = 0; nt < 16; nt++) {
#pragma unroll
                for (int kt2 = 0; kt2 < 2; kt2++) {
                    const int brow = kt2 * 32 + j * 8 + rr;
                    const int ch = nt ^ (brow & 7);
                    uint32_t vb[4];
                    ldsm_x4_t(vb, smem_u32(b_s + brow * 128 + ch * 8));
                    mma_bf16(cf[nt], qa[kt2 * 2],     vb[0], vb[1]);
                    mma_bf16(cf[nt], qa[kt2 * 2 + 1], vb[2], vb[3]);
                }
            }
        }
    }

    // ---- epilogue: + bias + residual, fp32 out ----
    const int row0 = m0 + w * 16 + (lane >> 2);
    const int row1 = row0 + 8;
#pragma unroll
    for (int nt = 0; nt < 16; nt++) {
        const int col = n0 + nt * 8 + (lane & 3) * 2;
        const float2 bb = *reinterpret_cast<const float2*>(bo + col);
        const float2 r0 = *reinterpret_cast<const float2*>(
            hs + (size_t)row0 * D_MODEL + col);
        const float2 r1 = *reinterpret_cast<const float2*>(
            hs + (size_t)row1 * D_MODEL + col);
        *reinterpret_cast<float2*>(outp + (size_t)row0 * D_MODEL + col) =
            make_float2(cf[nt][0] + bb.x + r0.x, cf[nt][1] + bb.y + r0.y);
        *reinterpret_cast<float2*>(outp + (size_t)row1 * D_MODEL + col) =
            make_float2(cf[nt][2] + bb.x + r1.x, cf[nt][3] + bb.y + r1.y);
    }
}

// ============================================================================
// Launch
// ============================================================================
extern "C" void kernel_launch(void* const* d_in, const int* in_sizes, int n_in,
                              void* d_out, int out_size)
{
    const float* hs        = (const float*)d_in[0];
    const float* p_out     = (const float*)d_in[1];
    const float* p_out_inv = (const float*)d_in[2];
    const float* Wq        = (const float*)d_in[3];
    const float* Wk        = (const float*)d_in[4];
    const float* Wv        = (const float*)d_in[5];
    const float* Wo        = (const float*)d_in[6];
    const float* bo        = (const float*)d_in[7];
    float* out             = (float*)d_out;

    qkv_mma_kernel<<<dim3(8, 32, 3), 256>>>(hs, Wq, Wk, Wv, p_out, p_out_inv);
    attn_kernel<<<dim3(64, 8), 128>>>();
    proj_mma_kernel<<<dim3(4, 32), 256>>>(Wo, bo, hs, out);
}

// round 11
// speedup vs baseline: 6.5504x; 1.1211x over previous
#include <cuda_runtime.h>
#include <cuda_bf16.h>
#include <cstdint>
#include <stdint.h>
#include <math.h>

// Problem constants (fixed by the reference):
//   B=1, T_OUT=8, L=512 -> S=4096 tokens, D=512, H=8 heads, hd=64
#define S_TOK   4096
#define D_MODEL 512
#define NH      8
#define HD      64

// Scratch (device globals: allocation-free, graph-safe).
__device__ __nv_bfloat16 g_qb[NH * S_TOK * HD];   // [h][s][hd], CAPE'd, scaled
__device__ __nv_bfloat16 g_kb[NH * S_TOK * HD];   // [h][s][hd], CAPE'd
__device__ __nv_bfloat16 g_vb[NH * S_TOK * HD];   // [h][s][hd]
__device__ __nv_bfloat16 g_ob[S_TOK * D_MODEL];   // attention output, (S, D) bf16

// ----------------------------------------------------------------------------
// PTX helpers: ldmatrix + bf16 mma (fp32 accum) + cp.async
// ----------------------------------------------------------------------------
__device__ __forceinline__ uint32_t smem_u32(const void* p) {
    return (uint32_t)__cvta_generic_to_shared(p);
}
__device__ __forceinline__ void ldsm_x4(uint32_t* r, uint32_t a) {
    asm volatile("ldmatrix.sync.aligned.m8n8.x4.shared.b16 {%0,%1,%2,%3}, [%4];"
                 : "=r"(r[0]), "=r"(r[1]), "=r"(r[2]), "=r"(r[3]) : "r"(a));
}
__device__ __forceinline__ void ldsm_x4_t(uint32_t* r, uint32_t a) {
    asm volatile("ldmatrix.sync.aligned.m8n8.x4.trans.shared.b16 {%0,%1,%2,%3}, [%4];"
                 : "=r"(r[0]), "=r"(r[1]), "=r"(r[2]), "=r"(r[3]) : "r"(a));
}
__device__ __forceinline__ void mma_bf16(float* c, const uint32_t* a,
                                         uint32_t b0, uint32_t b1) {
    asm volatile(
        "mma.sync.aligned.m16n8k16.row.col.f32.bf16.bf16.f32 "
        "{%0,%1,%2,%3}, {%4,%5,%6,%7}, {%8,%9}, {%0,%1,%2,%3};"
        : "+f"(c[0]), "+f"(c[1]), "+f"(c[2]), "+f"(c[3])
        : "r"(a[0]), "r"(a[1]), "r"(a[2]), "r"(a[3]), "r"(b0), "r"(b1));
}
__device__ __forceinline__ uint32_t pack_bf16x2(float a, float b) {
    __nv_bfloat162 t = __floats2bfloat162_rn(a, b);
    return *reinterpret_cast<uint32_t*>(&t);
}
__device__ __forceinline__ void cp_async16(uint32_t dst, const void* src) {
    asm volatile("cp.async.cg.shared.global [%0], [%1], 16;"
                 :: "r"(dst), "l"(src));
}
__device__ __forceinline__ void cp_commit() {
    asm volatile("cp.async.commit_group;");
}
template <int N>
__device__ __forceinline__ void cp_wait() {
    asm volatile("cp.async.wait_group %0;" :: "n"(N));
}

// ============================================================================
// Kernel 1: QKV projection on tensor cores + CAPE epilogue -> bf16 q/k/v.
//   BM=128, BN=64, BK=64; 256 threads; grid (8, 32, 3). (unchanged, 240us ver)
// ============================================================================
__global__ void __launch_bounds__(256, 2) qkv_mma_kernel(
    const float* __restrict__ x,
    const float* __restrict__ Wq, const float* __restrict__ Wk,
    const float* __restrict__ Wv,
    const float* __restrict__ p_out, const float* __restrict__ p_out_inv)
{
    __shared__ __nv_bfloat16 a_s[128 * 64];   // [m][k] swizzled (8 chunks/row)
    __shared__ __nv_bfloat16 b_s[64 * 64];    // [k][n] swizzled (8 chunks/row)

    const int mode = blockIdx.z;   // 0=q, 1=k, 2=v
    const float* __restrict__ W  = (mode == 0) ? Wq : (mode == 1) ? Wk : Wv;
    __nv_bfloat16* __restrict__ out =
        (mode == 0) ? g_qb : (mode == 1) ? g_kb : g_vb;
    const float* __restrict__ Pm = (mode == 0) ? p_out_inv : p_out;

    const int tid  = threadIdx.x;
    const int lane = tid & 31;
    const int w    = tid >> 5;
    const int m0   = blockIdx.y * 128;
    const int n0   = blockIdx.x * 64;

    float cf[8][4];
#pragma unroll
    for (int nt = 0; nt < 8; nt++)
#pragma unroll
        for (int c = 0; c < 4; c++) cf[nt][c] = 0.f;

    for (int k0 = 0; k0 < D_MODEL; k0 += 64) {
        __syncthreads();
#pragma unroll
        for (int u = 0; u < 4; u++) {
            const int gid = u * 256 + tid;
            const int row = gid >> 3;
            const int c8  = gid & 7;
            const float4* src = reinterpret_cast<const float4*>(
                x + (size_t)(m0 + row) * D_MODEL + k0 + c8 * 8);
            const float4 f0 = src[0], f1 = src[1];
            uint4 d;
            d.x = pack_bf16x2(f0.x, f0.y); d.y = pack_bf16x2(f0.z, f0.w);
            d.z = pack_bf16x2(f1.x, f1.y); d.w = pack_bf16x2(f1.z, f1.w);
            *reinterpret_cast<uint4*>(a_s + row * 64 + ((c8 ^ (row & 7)) << 3)) = d;
        }
#pragma unroll
        for (int u = 0; u < 2; u++) {
            const int gid = u * 256 + tid;
            const int row = gid >> 3;
            const int c8  = gid & 7;
            const float4* src = reinterpret_cast<const float4*>(
                W + (size_t)(k0 + row) * D_MODEL + n0 + c8 * 8);
            const float4 f0 = src[0], f1 = src[1];
            uint4 d;
            d.x = pack_bf16x2(f0.x, f0.y); d.y = pack_bf16x2(f0.z, f0.w);
            d.z = pack_bf16x2(f1.x, f1.y); d.w = pack_bf16x2(f1.z, f1.w);
            *reinterpret_cast<uint4*>(b_s + row * 64 + ((c8 ^ (row & 7)) << 3)) = d;
        }
        __syncthreads();

        uint32_t qa[4][4];
        {
            const int mi = lane >> 3, rr = lane & 7;
            const int arow = w * 16 + ((mi & 1) << 3) + rr;
#pragma unroll
            for (int kt = 0; kt < 4; kt++) {
                const int ch = (kt * 2 + (mi >> 1)) ^ (arow & 7);
                ldsm_x4(qa[kt], smem_u32(a_s + arow * 64 + ch * 8));
            }
        }
        {
            const int j = lane >> 3, rr = lane & 7;
#pragma unroll
            for (int nt = 0; nt < 8; nt++) {
#pragma unroll
                for (int kt2 = 0; kt2 < 2; kt2++) {
                    const int brow = kt2 * 32 + j * 8 + rr;
                    const int ch = nt ^ (brow & 7);
                    uint32_t vb[4];
                    ldsm_x4_t(vb, smem_u32(b_s + brow * 64 + ch * 8));
                    mma_bf16(cf[nt], qa[kt2 * 2],     vb[0], vb[1]);
                    mma_bf16(cf[nt], qa[kt2 * 2 + 1], vb[2], vb[3]);
                }
            }
        }
    }

    if (mode < 2) {
        const float* P = Pm + (m0 >> 9) * 16;
        float pm[16];
#pragma unroll
        for (int t = 0; t < 16; t++) pm[t] = P[t];
        const int gb = (lane & 1) * 2;
#pragma unroll
        for (int nt = 0; nt < 8; nt++) {
#pragma unroll
            for (int hf = 0; hf < 2; hf++) {
                const float v0 = cf[nt][hf * 2], v1 = cf[nt][hf * 2 + 1];
                const float p0 = __shfl_xor_sync(0xffffffffu, v0, 1);
                const float p1 = __shfl_xor_sync(0xffffffffu, v1, 1);
                const float a0 = (lane & 1) ? p0 : v0;
                const float a1 = (lane & 1) ? p1 : v1;
                const float a2 = (lane & 1) ? v0 : p0;
                const float a3 = (lane & 1) ? v1 : p1;
                cf[nt][hf * 2]     = a0 * pm[gb]     + a1 * pm[4 + gb]
                                   + a2 * pm[8 + gb] + a3 * pm[12 + gb];
                cf[nt][hf * 2 + 1] = a0 * pm[gb + 1]     + a1 * pm[4 + gb + 1]
                                   + a2 * pm[8 + gb + 1] + a3 * pm[12 + gb + 1];
            }
        }
    }
    if (mode == 0) {   // softmax scale * log2(e): 0.125 * 1.4426950
#pragma unroll
        for (int nt = 0; nt < 8; nt++)
#pragma unroll
            for (int c = 0; c < 4; c++) cf[nt][c] *= 0.18033688f;
    }

    const int row0 = m0 + w * 16 + (lane >> 2);
    const int row1 = row0 + 8;
#pragma unroll
    for (int nt = 0; nt < 8; nt++) {
        const int ng = n0 + nt * 8 + (lane & 3) * 2;
        const int h  = ng >> 6;
        const int c  = ng & 63;
        *reinterpret_cast<uint32_t*>(out + ((size_t)h * S_TOK + row0) * HD + c) =
            pack_bf16x2(cf[nt][0], cf[nt][1]);
        *reinterpret_cast<uint32_t*>(out + ((size_t)h * S_TOK + row1) * HD + c) =
            pack_bf16x2(cf[nt][2], cf[nt][3]);
    }
}

// ============================================================================
// Kernel 2: flash attention, bf16 mma, cp.async double-buffered K/V.
//   Br=64, Bc=128, 4 warps, 2 CTAs/SM. Dynamic smem 72KB:
//     q_s[64*64] | k_s[2][128*64] | v_s[2][128*64]
// ============================================================================
#define ATTN_SMEM_BYTES ((64 * 64 + 4 * 128 * 64) * 2)   // 73728 B

__global__ void __launch_bounds__(128, 2) attn_kernel()
{
    extern __shared__ __nv_bfloat16 sm[];
    __nv_bfloat16* q_s = sm;                        // 4096 elems
    __nv_bfloat16* k_b[2] = { sm + 4096,  sm + 4096 + 8192 };
    __nv_bfloat16* v_b[2] = { sm + 20480, sm + 20480 + 8192 };

    const int tid  = threadIdx.x;
    const int lane = tid & 31;
    const int w    = tid >> 5;          // warp 0..3 -> rows w*16..w*16+15
    const int h    = blockIdx.y;
    const int m0   = blockIdx.x * 64;

    const __nv_bfloat16* __restrict__ qg = g_qb + (size_t)h * S_TOK * HD;
    const __nv_bfloat16* __restrict__ kg = g_kb + (size_t)h * S_TOK * HD;
    const __nv_bfloat16* __restrict__ vg = g_vb + (size_t)h * S_TOK * HD;

    // ---- stage K/V tile for iteration `it` into buffer `buf` (async) ----
    auto stage_kv = [&](int it, int buf) {
        const __nv_bfloat16* ks = kg + (size_t)(it * 128) * HD;
        const __nv_bfloat16* vs = vg + (size_t)(it * 128) * HD;
#pragma unroll
        for (int u = 0; u < 8; u++) {
            const int gid = u * 128 + tid;  // 0..1023 16B chunks
            const int row = gid >> 3;
            const int c8  = gid & 7;
            const int so  = row * 64 + ((c8 ^ (row & 7)) << 3);
            cp_async16(smem_u32(k_b[buf] + so), ks + row * 64 + c8 * 8);
            cp_async16(smem_u32(v_b[buf] + so), vs + row * 64 + c8 * 8);
        }
    };

    // ---- load Q tile (64 rows, swizzled) ----
#pragma unroll
    for (int u = 0; u < 4; u++) {
        const int gid = u * 128 + tid;
        const int row = gid >> 3;
        const int c8  = gid & 7;
        uint4 d = *reinterpret_cast<const uint4*>(
            qg + (size_t)(m0 + row) * HD + c8 * 8);
        *reinterpret_cast<uint4*>(q_s + row * 64 + ((c8 ^ (row & 7)) << 3)) = d;
    }
    // prefetch iteration 0 K/V while we sync+load Q frags
    stage_kv(0, 0);
    cp_commit();
    __syncthreads();

    uint32_t qa[4][4];
    {
        const int mi = lane >> 3, rr = lane & 7;
        const int row = w * 16 + ((mi & 1) << 3) + rr;
#pragma unroll
        for (int kt = 0; kt < 4; kt++) {
            const int ch = (kt * 2 + (mi >> 1)) ^ (row & 7);
            ldsm_x4(qa[kt], smem_u32(q_s + row * 64 + ch * 8));
        }
    }

    float m_i0 = -1e30f, m_i1 = -1e30f, l0 = 0.f, l1 = 0.f;
    float of[8][4];
#pragma unroll
    for (int nt = 0; nt < 8; nt++)
#pragma unroll
        for (int c = 0; c < 4; c++) of[nt][c] = 0.f;

    const int NIT = S_TOK / 128;   // 32
    for (int it = 0; it < NIT; it++) {
        const int buf = it & 1;
        // issue next tile's loads into the other buffer, then wait for ours
        if (it + 1 < NIT) {
            stage_kv(it + 1, buf ^ 1);
            cp_commit();
            cp_wait<1>();          // group `it` complete; `it+1` in flight
        } else {
            cp_wait<0>();
        }
        __syncthreads();           // buf's data visible to all warps

        const __nv_bfloat16* k_s = k_b[buf];
        const __nv_bfloat16* v_s = v_b[buf];

        // ---- S = Q K^T : 16 n-tiles x 4 k-steps (non-trans K frags) ----
        float sf[16][4];
#pragma unroll
        for (int nt = 0; nt < 16; nt++)
#pragma unroll
            for (int c = 0; c < 4; c++) sf[nt][c] = 0.f;

        {
            const int j = lane >> 3, rr = lane & 7;
#pragma unroll
            for (int nt = 0; nt < 16; nt++) {
                const int srow = nt * 8 + rr;
                uint32_t b[8];
                const int ch0 = (j)     ^ (srow & 7);
                const int ch1 = (4 + j) ^ (srow & 7);
                ldsm_x4(b,     smem_u32(k_s + srow * 64 + ch0 * 8));
                ldsm_x4(b + 4, smem_u32(k_s + srow * 64 + ch1 * 8));
                mma_bf16(sf[nt], qa[0], b[0], b[1]);
                mma_bf16(sf[nt], qa[1], b[2], b[3]);
                mma_bf16(sf[nt], qa[2], b[4], b[5]);
                mma_bf16(sf[nt], qa[3], b[6], b[7]);
            }
        }

        // ---- online softmax in exp2 domain (scores pre-scaled by log2 e) ----
        float mx0 = sf[0][0], mx1 = sf[0][2];
#pragma unroll
        for (int nt = 0; nt < 16; nt++) {
            mx0 = fmaxf(mx0, fmaxf(sf[nt][0], sf[nt][1]));
            mx1 = fmaxf(mx1, fmaxf(sf[nt][2], sf[nt][3]));
        }
        mx0 = fmaxf(mx0, __shfl_xor_sync(0xffffffffu, mx0, 1));
        mx0 = fmaxf(mx0, __shfl_xor_sync(0xffffffffu, mx0, 2));
        mx1 = fmaxf(mx1, __shfl_xor_sync(0xffffffffu, mx1, 1));
        mx1 = fmaxf(mx1, __shfl_xor_sync(0xffffffffu, mx1, 2));

        const float mn0 = fmaxf(m_i0, mx0);
        const float mn1 = fmaxf(m_i1, mx1);
        const float al0 = exp2f(m_i0 - mn0);
        const float al1 = exp2f(m_i1 - mn1);
        m_i0 = mn0; m_i1 = mn1;

        float rs0 = 0.f, rs1 = 0.f;
        uint32_t pa[8][4];   // P A-frags for PV (k = 128 -> 8 k-tiles)
#pragma unroll
        for (int nt = 0; nt < 16; nt++) {
            const float e0 = exp2f(sf[nt][0] - mn0);
            const float e1 = exp2f(sf[nt][1] - mn0);
            const float e2 = exp2f(sf[nt][2] - mn1);
            const float e3 = exp2f(sf[nt][3] - mn1);
            rs0 += e0 + e1; rs1 += e2 + e3;
            const uint32_t p01 = pack_bf16x2(e0, e1);
            const uint32_t p23 = pack_bf16x2(e2, e3);
            const int jt = nt >> 1;
            if ((nt & 1) == 0) { pa[jt][0] = p01; pa[jt][1] = p23; }
            else               { pa[jt][2] = p01; pa[jt][3] = p23; }
        }
        rs0 += __shfl_xor_sync(0xffffffffu, rs0, 1);
        rs0 += __shfl_xor_sync(0xffffffffu, rs0, 2);
        rs1 += __shfl_xor_sync(0xffffffffu, rs1, 1);
        rs1 += __shfl_xor_sync(0xffffffffu, rs1, 2);
        l0 = l0 * al0 + rs0;
        l1 = l1 * al1 + rs1;

#pragma unroll
        for (int nt = 0; nt < 8; nt++) {
            of[nt][0] *= al0; of[nt][1] *= al0;
            of[nt][2] *= al1; of[nt][3] *= al1;
        }

        // ---- O += P V : trans V frags ----
        {
            const int j = lane >> 3, rr = lane & 7;
#pragma unroll
            for (int kt2 = 0; kt2 < 4; kt2++) {
                const int vrow = kt2 * 32 + j * 8 + rr;
#pragma unroll
                for (int nt = 0; nt < 8; nt++) {
                    uint32_t vb[4];
                    const int ch = nt ^ (vrow & 7);
                    ldsm_x4_t(vb, smem_u32(v_s + vrow * 64 + ch * 8));
                    mma_bf16(of[nt], pa[2 * kt2],     vb[0], vb[1]);
                    mma_bf16(of[nt], pa[2 * kt2 + 1], vb[2], vb[3]);
                }
            }
        }
        __syncthreads();   // all warps done with buf before it is overwritten
    }

    // ---- normalize + store bf16 to (S, D) layout ----
    const float inv0 = 1.0f / l0;
    const float inv1 = 1.0f / l1;
    const int row0 = m0 + w * 16 + (lane >> 2);
    const int row1 = row0 + 8;
    const int cbase = h * HD + (lane & 3) * 2;
#pragma unroll
    for (int nt = 0; nt < 8; nt++) {
        const int col = cbase + nt * 8;
        *reinterpret_cast<uint32_t*>(g_ob + (size_t)row0 * D_MODEL + col) =
            pack_bf16x2(of[nt][0] * inv0, of[nt][1] * inv0);
        *reinterpret_cast<uint32_t*>(g_ob + (size_t)row1 * D_MODEL + col) =
            pack_bf16x2(of[nt][2] * inv1, of[nt][3] * inv1);
    }
}

// ============================================================================
// Kernel 3: output projection on tensor cores + bias + residual (fp32 out).
//   Unchanged from the 240us version. grid (4, 32), block 256.
// ============================================================================
__global__ void __launch_bounds__(256) proj_mma_kernel(
    const float* __restrict__ Wo, const float* __restrict__ bo,
    const float* __restrict__ hs, float* __restrict__ outp)
{
    __shared__ __nv_bfloat16 a_s[128 * 64];
    __shared__ __nv_bfloat16 b_s[64 * 128];

    const int tid  = threadIdx.x;
    const int lane = tid & 31;
    const int w    = tid >> 5;
    const int m0   = blockIdx.y * 128;
    const int n0   = blockIdx.x * 128;

    float cf[16][4];
#pragma unroll
    for (int nt = 0; nt < 16; nt++)
#pragma unroll
        for (int c = 0; c < 4; c++) cf[nt][c] = 0.f;

    for (int k0 = 0; k0 < D_MODEL; k0 += 64) {
        __syncthreads();
#pragma unroll
        for (int u = 0; u < 4; u++) {
            const int gid = u * 256 + tid;
            const int row = gid >> 3;
            const int c8  = gid & 7;
            uint4 d = *reinterpret_cast<const uint4*>(
                g_ob + (size_t)(m0 + row) * D_MODEL + k0 + c8 * 8);
            *reinterpret_cast<uint4*>(a_s + row * 64 + ((c8 ^ (row & 7)) << 3)) = d;
        }
#pragma unroll
        for (int u = 0; u < 4; u++) {
            const int gid = u * 256 + tid;
            const int row = gid >> 4;
            const int c16 = gid & 15;
            const float4* src = reinterpret_cast<const float4*>(
                Wo + (size_t)(k0 + row) * D_MODEL + n0 + c16 * 8);
            const float4 f0 = src[0], f1 = src[1];
            uint4 d;
            d.x = pack_bf16x2(f0.x, f0.y); d.y = pack_bf16x2(f0.z, f0.w);
            d.z = pack_bf16x2(f1.x, f1.y); d.w = pack_bf16x2(f1.z, f1.w);
            *reinterpret_cast<uint4*>(b_s + row * 128 + ((c16 ^ (row & 7)) << 3)) = d;
        }
        __syncthreads();

        uint32_t qa[4][4];
        {
            const int mi = lane >> 3, rr = lane & 7;
            const int arow = w * 16 + ((mi & 1) << 3) + rr;
#pragma unroll
            for (int kt = 0; kt < 4; kt++) {
                const int ch = (kt * 2 + (mi >> 1)) ^ (arow & 7);
                ldsm_x4(qa[kt], smem_u32(a_s + arow * 64 + ch * 8));
            }
        }
        {
            const int j = lane >> 3, rr = lane & 7;
#pragma unroll
            for (int nt = 0; nt < 16; nt++) {
#pragma unroll
                for (int kt2 = 0; kt2 < 2; kt2++) {
                    const int brow = kt2 * 32 + j * 8 + rr;
                    const int ch = nt ^ (brow & 7);
                    uint32_t vb[4];
                    ldsm_x4_t(vb, smem_u32(b_s + brow * 128 + ch * 8));
                    mma_bf16(cf[nt], qa[kt2 * 2],     vb[0], vb[1]);
                    mma_bf16(cf[nt], qa[kt2 * 2 + 1], vb[2], vb[3]);
                }
            }
        }
    }

    const int row0 = m0 + w * 16 + (lane >> 2);
    const int row1 = row0 + 8;
#pragma unroll
    for (int nt = 0; nt < 16; nt++) {
        const int col = n0 + nt * 8 + (lane & 3) * 2;
        const float2 bb = *reinterpret_cast<const float2*>(bo + col);
        const float2 r0 = *reinterpret_cast<const float2*>(
            hs + (size_t)row0 * D_MODEL + col);
        const float2 r1 = *reinterpret_cast<const float2*>(
            hs + (size_t)row1 * D_MODEL + col);
        *reinterpret_cast<float2*>(outp + (size_t)row0 * D_MODEL + col) =
            make_float2(cf[nt][0] + bb.x + r0.x, cf[nt][1] + bb.y + r0.y);
        *reinterpret_cast<float2*>(outp + (size_t)row1 * D_MODEL + col) =
            make_float2(cf[nt][2] + bb.x + r1.x, cf[nt][3] + bb.y + r1.y);
    }
}

// ============================================================================
// Launch
// ============================================================================
extern "C" void kernel_launch(void* const* d_in, const int* in_sizes, int n_in,
                              void* d_out, int out_size)
{
    const float* hs        = (const float*)d_in[0];
    const float* p_out     = (const float*)d_in[1];
    const float* p_out_inv = (const float*)d_in[2];
    const float* Wq        = (const float*)d_in[3];
    const float* Wk        = (const float*)d_in[4];
    const float* Wv        = (const float*)d_in[5];
    const float* Wo        = (const float*)d_in[6];
    const float* bo        = (const float*)d_in[7];
    float* out             = (float*)d_out;

    // >48KB dynamic smem opt-in (host attribute; idempotent, graph-safe).
    cudaFuncSetAttribute(attn_kernel,
                         cudaFuncAttributeMaxDynamicSharedMemorySize,
                         ATTN_SMEM_BYTES);

    qkv_mma_kernel<<<dim3(8, 32, 3), 256>>>(hs, Wq, Wk, Wv, p_out, p_out_inv);
    attn_kernel<<<dim3(64, 8), 128, ATTN_SMEM_BYTES>>>();
    proj_mma_kernel<<<dim3(4, 32), 256>>>(Wo, bo, hs, out);
}

// round 14
// speedup vs baseline: 7.4186x; 1.1325x over previous
#include <cuda_runtime.h>
#include <cuda_bf16.h>
#include <cstdint>
#include <stdint.h>
#include <math.h>

// Problem constants (fixed by the reference):
//   B=1, T_OUT=8, L=512 -> S=4096 tokens, D=512, H=8 heads, hd=64
#define S_TOK   4096
#define D_MODEL 512
#define NH      8
#define HD      64

// Scratch (device globals: allocation-free, graph-safe).
__device__ __nv_bfloat16 g_xb[S_TOK * D_MODEL];       // x in bf16
__device__ __nv_bfloat16 g_wb[4 * D_MODEL * D_MODEL]; // Wq|Wk|Wv|Wo in bf16
__device__ __nv_bfloat16 g_qb[NH * S_TOK * HD];       // q, CAPE'd, scaled
__device__ __nv_bfloat16 g_kb[NH * S_TOK * HD];       // k, CAPE'd
__device__ __nv_bfloat16 g_vb[NH * S_TOK * HD];       // v
__device__ __nv_bfloat16 g_ob[S_TOK * D_MODEL];       // attention out (S, D)

// ----------------------------------------------------------------------------
// PTX helpers
// ----------------------------------------------------------------------------
__device__ __forceinline__ uint32_t smem_u32(const void* p) {
    return (uint32_t)__cvta_generic_to_shared(p);
}
__device__ __forceinline__ void ldsm_x4(uint32_t* r, uint32_t a) {
    asm volatile("ldmatrix.sync.aligned.m8n8.x4.shared.b16 {%0,%1,%2,%3}, [%4];"
                 : "=r"(r[0]), "=r"(r[1]), "=r"(r[2]), "=r"(r[3]) : "r"(a));
}
__device__ __forceinline__ void ldsm_x4_t(uint32_t* r, uint32_t a) {
    asm volatile("ldmatrix.sync.aligned.m8n8.x4.trans.shared.b16 {%0,%1,%2,%3}, [%4];"
                 : "=r"(r[0]), "=r"(r[1]), "=r"(r[2]), "=r"(r[3]) : "r"(a));
}
__device__ __forceinline__ void mma_bf16(float* c, const uint32_t* a,
                                         uint32_t b0, uint32_t b1) {
    asm volatile(
        "mma.sync.aligned.m16n8k16.row.col.f32.bf16.bf16.f32 "
        "{%0,%1,%2,%3}, {%4,%5,%6,%7}, {%8,%9}, {%0,%1,%2,%3};"
        : "+f"(c[0]), "+f"(c[1]), "+f"(c[2]), "+f"(c[3])
        : "r"(a[0]), "r"(a[1]), "r"(a[2]), "r"(a[3]), "r"(b0), "r"(b1));
}
__device__ __forceinline__ uint32_t pack_bf16x2(float a, float b) {
    __nv_bfloat162 t = __floats2bfloat162_rn(a, b);
    return *reinterpret_cast<uint32_t*>(&t);
}
__device__ __forceinline__ void cp_async16(uint32_t dst, const void* src) {
    asm volatile("cp.async.cg.shared.global [%0], [%1], 16;"
                 :: "r"(dst), "l"(src));
}
__device__ __forceinline__ void cp_commit() {
    asm volatile("cp.async.commit_group;");
}
template <int N>
__device__ __forceinline__ void cp_wait() {
    asm volatile("cp.async.wait_group %0;" :: "n"(N));
}

// ============================================================================
// Kernel 0: fp32 -> bf16 conversion of x and all weights (streaming).
//   Virtual concat [x | Wq | Wk | Wv | Wo], 8 elems/thread. 1536 blocks x 256.
// ============================================================================
#define X_CHUNKS  (S_TOK * D_MODEL / 8)            // 262144
#define W_CHUNKS  (D_MODEL * D_MODEL / 8)          // 32768

__global__ void __launch_bounds__(256) convert_kernel(
    const float* __restrict__ x,
    const float* __restrict__ Wq, const float* __restrict__ Wk,
    const float* __restrict__ Wv, const float* __restrict__ Wo)
{
    const int gid = blockIdx.x * 256 + threadIdx.x;   // chunk index (8 elems)
    const float* src;
    __nv_bfloat16* dst;
    int off;
    if (gid < X_CHUNKS)                     { src = x;  dst = g_xb;                          off = gid; }
    else if (gid < X_CHUNKS + W_CHUNKS)     { src = Wq; dst = g_wb;                          off = gid - X_CHUNKS; }
    else if (gid < X_CHUNKS + 2 * W_CHUNKS) { src = Wk; dst = g_wb + D_MODEL * D_MODEL;      off = gid - X_CHUNKS - W_CHUNKS; }
    else if (gid < X_CHUNKS + 3 * W_CHUNKS) { src = Wv; dst = g_wb + 2 * D_MODEL * D_MODEL;  off = gid - X_CHUNKS - 2 * W_CHUNKS; }
    else                                    { src = Wo; dst = g_wb + 3 * D_MODEL * D_MODEL;  off = gid - X_CHUNKS - 3 * W_CHUNKS; }

    const float4* s = reinterpret_cast<const float4*>(src) + (size_t)off * 2;
    const float4 f0 = s[0], f1 = s[1];
    uint4 d;
    d.x = pack_bf16x2(f0.x, f0.y); d.y = pack_bf16x2(f0.z, f0.w);
    d.z = pack_bf16x2(f1.x, f1.y); d.w = pack_bf16x2(f1.z, f1.w);
    *reinterpret_cast<uint4*>(dst + (size_t)off * 8) = d;
}

// ============================================================================
// Kernel 1: QKV projection, cp.async double-buffered bf16 tiles.
//   BM=128, BN=64, BK=64; 256 threads; 2 CTAs/SM; grid (8, 32, 3).
//   smem: a[2][128*64] + b[2][64*64] bf16 = 49152 B dynamic.
// ============================================================================
#define QKV_SMEM_BYTES ((2 * 128 * 64 + 2 * 64 * 64) * 2)   // 49152

__global__ void __launch_bounds__(256, 2) qkv_mma_kernel(
    const float* __restrict__ p_out, const float* __restrict__ p_out_inv)
{
    extern __shared__ __nv_bfloat16 smq[];
    __nv_bfloat16* a_b[2] = { smq,          smq + 8192 };
    __nv_bfloat16* b_b[2] = { smq + 16384,  smq + 16384 + 4096 };

    const int mode = blockIdx.z;   // 0=q, 1=k, 2=v
    const __nv_bfloat16* __restrict__ W = g_wb + (size_t)mode * D_MODEL * D_MODEL;
    __nv_bfloat16* __restrict__ out =
        (mode == 0) ? g_qb : (mode == 1) ? g_kb : g_vb;
    const float* __restrict__ Pm = (mode == 0) ? p_out_inv : p_out;

    const int tid  = threadIdx.x;
    const int lane = tid & 31;
    const int w    = tid >> 5;
    const int m0   = blockIdx.y * 128;
    const int n0   = blockIdx.x * 64;

    // stage A(128x64)+B(64x64) bf16 tiles for k-step `ks` into buffer `buf`
    auto stage = [&](int ks, int buf) {
        const int k0 = ks * 64;
#pragma unroll
        for (int u = 0; u < 4; u++) {
            const int gid = u * 256 + tid;      // 0..1023 chunks (A)
            const int row = gid >> 3;
            const int c8  = gid & 7;
            cp_async16(smem_u32(a_b[buf] + row * 64 + ((c8 ^ (row & 7)) << 3)),
                       g_xb + (size_t)(m0 + row) * D_MODEL + k0 + c8 * 8);
        }
#pragma unroll
        for (int u = 0; u < 2; u++) {
            const int gid = u * 256 + tid;      // 0..511 chunks (B)
            const int row = gid >> 3;
            const int c8  = gid & 7;
            cp_async16(smem_u32(b_b[buf] + row * 64 + ((c8 ^ (row & 7)) << 3)),
                       W + (size_t)(k0 + row) * D_MODEL + n0 + c8 * 8);
        }
    };

    float cf[8][4];
#pragma unroll
    for (int nt = 0; nt < 8; nt++)
#pragma unroll
        for (int c = 0; c < 4; c++) cf[nt][c] = 0.f;

    stage(0, 0);
    cp_commit();

    const int NKS = D_MODEL / 64;   // 8
    for (int ks = 0; ks < NKS; ks++) {
        const int buf = ks & 1;
        if (ks + 1 < NKS) {
            stage(ks + 1, buf ^ 1);
            cp_commit();
            cp_wait<1>();
        } else {
            cp_wait<0>();
        }
        __syncthreads();

        const __nv_bfloat16* a_s = a_b[buf];
        const __nv_bfloat16* b_s = b_b[buf];

        uint32_t qa[4][4];
        {
            const int mi = lane >> 3, rr = lane & 7;
            const int arow = w * 16 + ((mi & 1) << 3) + rr;
#pragma unroll
            for (int kt = 0; kt < 4; kt++) {
                const int ch = (kt * 2 + (mi >> 1)) ^ (arow & 7);
                ldsm_x4(qa[kt], smem_u32(a_s + arow * 64 + ch * 8));
            }
        }
        {
            const int j = lane >> 3, rr = lane & 7;
#pragma unroll
            for (int nt = 0; nt < 8; nt++) {
#pragma unroll
                for (int kt2 = 0; kt2 < 2; kt2++) {
                    const int brow = kt2 * 32 + j * 8 + rr;
                    const int ch = nt ^ (brow & 7);
                    uint32_t vb[4];
                    ldsm_x4_t(vb, smem_u32(b_s + brow * 64 + ch * 8));
                    mma_bf16(cf[nt], qa[kt2 * 2],     vb[0], vb[1]);
                    mma_bf16(cf[nt], qa[kt2 * 2 + 1], vb[2], vb[3]);
                }
            }
        }
        __syncthreads();
    }

    // ---- CAPE epilogue (q,k): mix 4-col groups via shfl_xor(1). ----
    if (mode < 2) {
        const float* P = Pm + (m0 >> 9) * 16;
        float pm[16];
#pragma unroll
        for (int t = 0; t < 16; t++) pm[t] = P[t];
        const int gb = (lane & 1) * 2;
#pragma unroll
        for (int nt = 0; nt < 8; nt++) {
#pragma unroll
            for (int hf = 0; hf < 2; hf++) {
                const float v0 = cf[nt][hf * 2], v1 = cf[nt][hf * 2 + 1];
                const float p0 = __shfl_xor_sync(0xffffffffu, v0, 1);
                const float p1 = __shfl_xor_sync(0xffffffffu, v1, 1);
                const float a0 = (lane & 1) ? p0 : v0;
                const float a1 = (lane & 1) ? p1 : v1;
                const float a2 = (lane & 1) ? v0 : p0;
                const float a3 = (lane & 1) ? v1 : p1;
                cf[nt][hf * 2]     = a0 * pm[gb]     + a1 * pm[4 + gb]
                                   + a2 * pm[8 + gb] + a3 * pm[12 + gb];
                cf[nt][hf * 2 + 1] = a0 * pm[gb + 1]     + a1 * pm[4 + gb + 1]
                                   + a2 * pm[8 + gb + 1] + a3 * pm[12 + gb + 1];
            }
        }
    }
    if (mode == 0) {   // softmax scale * log2(e): 0.125 * 1.4426950
#pragma unroll
        for (int nt = 0; nt < 8; nt++)
#pragma unroll
            for (int c = 0; c < 4; c++) cf[nt][c] *= 0.18033688f;
    }

    const int row0 = m0 + w * 16 + (lane >> 2);
    const int row1 = row0 + 8;
#pragma unroll
    for (int nt = 0; nt < 8; nt++) {
        const int ng = n0 + nt * 8 + (lane & 3) * 2;
        const int h  = ng >> 6;
        const int c  = ng & 63;
        *reinterpret_cast<uint32_t*>(out + ((size_t)h * S_TOK + row0) * HD + c) =
            pack_bf16x2(cf[nt][0], cf[nt][1]);
        *reinterpret_cast<uint32_t*>(out + ((size_t)h * S_TOK + row1) * HD + c) =
            pack_bf16x2(cf[nt][2], cf[nt][3]);
    }
}

// ============================================================================
// Kernel 2: flash attention (unchanged from 214us version).
//   Br=64, Bc=128, 4 warps, 2 CTAs/SM, cp.async double-buffered K/V.
// ============================================================================
#define ATTN_SMEM_BYTES ((64 * 64 + 4 * 128 * 64) * 2)   // 73728 B

__global__ void __launch_bounds__(128, 2) attn_kernel()
{
    extern __shared__ __nv_bfloat16 sm[];
    __nv_bfloat16* q_s = sm;
    __nv_bfloat16* k_b[2] = { sm + 4096,  sm + 4096 + 8192 };
    __nv_bfloat16* v_b[2] = { sm + 20480, sm + 20480 + 8192 };

    const int tid  = threadIdx.x;
    const int lane = tid & 31;
    const int w    = tid >> 5;
    const int h    = blockIdx.y;
    const int m0   = blockIdx.x * 64;

    const __nv_bfloat16* __restrict__ qg = g_qb + (size_t)h * S_TOK * HD;
    const __nv_bfloat16* __restrict__ kg = g_kb + (size_t)h * S_TOK * HD;
    const __nv_bfloat16* __restrict__ vg = g_vb + (size_t)h * S_TOK * HD;

    auto stage_kv = [&](int it, int buf) {
        const __nv_bfloat16* ks = kg + (size_t)(it * 128) * HD;
        const __nv_bfloat16* vs = vg + (size_t)(it * 128) * HD;
#pragma unroll
        for (int u = 0; u < 8; u++) {
            const int gid = u * 128 + tid;
            const int row = gid >> 3;
            const int c8  = gid & 7;
            const int so  = row * 64 + ((c8 ^ (row & 7)) << 3);
            cp_async16(smem_u32(k_b[buf] + so), ks + row * 64 + c8 * 8);
            cp_async16(smem_u32(v_b[buf] + so), vs + row * 64 + c8 * 8);
        }
    };

#pragma unroll
    for (int u = 0; u < 4; u++) {
        const int gid = u * 128 + tid;
        const int row = gid >> 3;
        const int c8  = gid & 7;
        uint4 d = *reinterpret_cast<const uint4*>(
            qg + (size_t)(m0 + row) * HD + c8 * 8);
        *reinterpret_cast<uint4*>(q_s + row * 64 + ((c8 ^ (row & 7)) << 3)) = d;
    }
    stage_kv(0, 0);
    cp_commit();
    __syncthreads();

    uint32_t qa[4][4];
    {
        const int mi = lane >> 3, rr = lane & 7;
        const int row = w * 16 + ((mi & 1) << 3) + rr;
#pragma unroll
        for (int kt = 0; kt < 4; kt++) {
            const int ch = (kt * 2 + (mi >> 1)) ^ (row & 7);
            ldsm_x4(qa[kt], smem_u32(q_s + row * 64 + ch * 8));
        }
    }

    float m_i0 = -1e30f, m_i1 = -1e30f, l0 = 0.f, l1 = 0.f;
    float of[8][4];
#pragma unroll
    for (int nt = 0; nt < 8; nt++)
#pragma unroll
        for (int c = 0; c < 4; c++) of[nt][c] = 0.f;

    const int NIT = S_TOK / 128;   // 32
    for (int it = 0; it < NIT; it++) {
        const int buf = it & 1;
        if (it + 1 < NIT) {
            stage_kv(it + 1, buf ^ 1);
            cp_commit();
            cp_wait<1>();
        } else {
            cp_wait<0>();
        }
        __syncthreads();

        const __nv_bfloat16* k_s = k_b[buf];
        const __nv_bfloat16* v_s = v_b[buf];

        float sf[16][4];
#pragma unroll
        for (int nt = 0; nt < 16; nt++)
#pragma unroll
            for (int c = 0; c < 4; c++) sf[nt][c] = 0.f;

        {
            const int j = lane >> 3, rr = lane & 7;
#pragma unroll
            for (int nt = 0; nt < 16; nt++) {
                const int srow = nt * 8 + rr;
                uint32_t b[8];
                const int ch0 = (j)     ^ (srow & 7);
                const int ch1 = (4 + j) ^ (srow & 7);
                ldsm_x4(b,     smem_u32(k_s + srow * 64 + ch0 * 8));
                ldsm_x4(b + 4, smem_u32(k_s + srow * 64 + ch1 * 8));
                mma_bf16(sf[nt], qa[0], b[0], b[1]);
                mma_bf16(sf[nt], qa[1], b[2], b[3]);
                mma_bf16(sf[nt], qa[2], b[4], b[5]);
                mma_bf16(sf[nt], qa[3], b[6], b[7]);
            }
        }

        float mx0 = sf[0][0], mx1 = sf[0][2];
#pragma unroll
        for (int nt = 0; nt < 16; nt++) {
            mx0 = fmaxf(mx0, fmaxf(sf[nt][0], sf[nt][1]));
            mx1 = fmaxf(mx1, fmaxf(sf[nt][2], sf[nt][3]));
        }
        mx0 = fmaxf(mx0, __shfl_xor_sync(0xffffffffu, mx0, 1));
        mx0 = fmaxf(mx0, __shfl_xor_sync(0xffffffffu, mx0, 2));
        mx1 = fmaxf(mx1, __shfl_xor_sync(0xffffffffu, mx1, 1));
        mx1 = fmaxf(mx1, __shfl_xor_sync(0xffffffffu, mx1, 2));

        const float mn0 = fmaxf(m_i0, mx0);
        const float mn1 = fmaxf(m_i1, mx1);
        const float al0 = exp2f(m_i0 - mn0);
        const float al1 = exp2f(m_i1 - mn1);
        m_i0 = mn0; m_i1 = mn1;

        float rs0 = 0.f, rs1 = 0.f;
        uint32_t pa[8][4];
#pragma unroll
        for (int nt = 0; nt < 16; nt++) {
            const float e0 = exp2f(sf[nt][0] - mn0);
            const float e1 = exp2f(sf[nt][1] - mn0);
            const float e2 = exp2f(sf[nt][2] - mn1);
            const float e3 = exp2f(sf[nt][3] - mn1);
            rs0 += e0 + e1; rs1 += e2 + e3;
            const uint32_t p01 = pack_bf16x2(e0, e1);
            const uint32_t p23 = pack_bf16x2(e2, e3);
            const int jt = nt >> 1;
            if ((nt & 1) == 0) { pa[jt][0] = p01; pa[jt][1] = p23; }
            else               { pa[jt][2] = p01; pa[jt][3] = p23; }
        }
        rs0 += __shfl_xor_sync(0xffffffffu, rs0, 1);
        rs0 += __shfl_xor_sync(0xffffffffu, rs0, 2);
        rs1 += __shfl_xor_sync(0xffffffffu, rs1, 1);
        rs1 += __shfl_xor_sync(0xffffffffu, rs1, 2);
        l0 = l0 * al0 + rs0;
        l1 = l1 * al1 + rs1;

#pragma unroll
        for (int nt = 0; nt < 8; nt++) {
            of[nt][0] *= al0; of[nt][1] *= al0;
            of[nt][2] *= al1; of[nt][3] *= al1;
        }

        {
            const int j = lane >> 3, rr = lane & 7;
#pragma unroll
            for (int kt2 = 0; kt2 < 4; kt2++) {
                const int vrow = kt2 * 32 + j * 8 + rr;
#pragma unroll
                for (int nt = 0; nt < 8; nt++) {
                    uint32_t vb[4];
                    const int ch = nt ^ (vrow & 7);
                    ldsm_x4_t(vb, smem_u32(v_s + vrow * 64 + ch * 8));
                    mma_bf16(of[nt], pa[2 * kt2],     vb[0], vb[1]);
                    mma_bf16(of[nt], pa[2 * kt2 + 1], vb[2], vb[3]);
                }
            }
        }
        __syncthreads();
    }

    const float inv0 = 1.0f / l0;
    const float inv1 = 1.0f / l1;
    const int row0 = m0 + w * 16 + (lane >> 2);
    const int row1 = row0 + 8;
    const int cbase = h * HD + (lane & 3) * 2;
#pragma unroll
    for (int nt = 0; nt < 8; nt++) {
        const int col = cbase + nt * 8;
        *reinterpret_cast<uint32_t*>(g_ob + (size_t)row0 * D_MODEL + col) =
            pack_bf16x2(of[nt][0] * inv0, of[nt][1] * inv0);
        *reinterpret_cast<uint32_t*>(g_ob + (size_t)row1 * D_MODEL + col) =
            pack_bf16x2(of[nt][2] * inv1, of[nt][3] * inv1);
    }
}

// ============================================================================
// Kernel 3: output projection, cp.async double-buffered; bias + residual.
//   BM=128, BN=128, BK=64; 256 threads; grid (4, 32). smem 64KB dynamic.
// ============================================================================
#define PROJ_SMEM_BYTES ((2 * 128 * 64 + 2 * 64 * 128) * 2)   // 65536

__global__ void __launch_bounds__(256) proj_mma_kernel(
    const float* __restrict__ bo,
    const float* __restrict__ hs, float* __restrict__ outp)
{
    extern __shared__ __nv_bfloat16 smp[];
    __nv_bfloat16* a_b[2] = { smp,          smp + 8192 };
    __nv_bfloat16* b_b[2] = { smp + 16384,  smp + 16384 + 8192 };

    const __nv_bfloat16* __restrict__ Wo = g_wb + (size_t)3 * D_MODEL * D_MODEL;

    const int tid  = threadIdx.x;
    const int lane = tid & 31;
    const int w    = tid >> 5;
    const int m0   = blockIdx.y * 128;
    const int n0   = blockIdx.x * 128;

    auto stage = [&](int ks, int buf) {
        const int k0 = ks * 64;
#pragma unroll
        for (int u = 0; u < 4; u++) {
            const int gid = u * 256 + tid;      // A: 128x64, 1024 chunks
            const int row = gid >> 3;
            const int c8  = gid & 7;
            cp_async16(smem_u32(a_b[buf] + row * 64 + ((c8 ^ (row & 7)) << 3)),
                       g_ob + (size_t)(m0 + row) * D_MODEL + k0 + c8 * 8);
        }
#pragma unroll
        for (int u = 0; u < 4; u++) {
            const int gid = u * 256 + tid;      // B: 64x128, 1024 chunks
            const int row = gid >> 4;
            const int c16 = gid & 15;
            cp_async16(smem_u32(b_b[buf] + row * 128 + ((c16 ^ (row & 7)) << 3)),
                       Wo + (size_t)(k0 + row) * D_MODEL + n0 + c16 * 8);
        }
    };

    float cf[16][4];
#pragma unroll
    for (int nt = 0; nt < 16; nt++)
#pragma unroll
        for (int c = 0; c < 4; c++) cf[nt][c] = 0.f;

    stage(0, 0);
    cp_commit();

    const int NKS = D_MODEL / 64;   // 8
    for (int ks = 0; ks < NKS; ks++) {
        const int buf = ks & 1;
        if (ks + 1 < NKS) {
            stage(ks + 1, buf ^ 1);
            cp_commit();
            cp_wait<1>();
        } else {
            cp_wait<0>();
        }
        __syncthreads();

        const __nv_bfloat16* a_s = a_b[buf];
        const __nv_bfloat16* b_s = b_b[buf];

        uint32_t qa[4][4];
        {
            const int mi = lane >> 3, rr = lane & 7;
            const int arow = w * 16 + ((mi & 1) << 3) + rr;
#pragma unroll
            for (int kt = 0; kt < 4; kt++) {
                const int ch = (kt * 2 + (mi >> 1)) ^ (arow & 7);
                ldsm_x4(qa[kt], smem_u32(a_s + arow * 64 + ch * 8));
            }
        }
        {
            const int j = lane >> 3, rr = lane & 7;
#pragma unroll
            for (int nt = 0; nt < 16; nt++) {
#pragma unroll
                for (int kt2 = 0; kt2 < 2; kt2++) {
                    const int brow = kt2 * 32 + j * 8 + rr;
                    const int ch = nt ^ (brow & 7);
                    uint32_t vb[4];
                    ldsm_x4_t(vb, smem_u32(b_s + brow * 128 + ch * 8));
                    mma_bf16(cf[nt], qa[kt2 * 2],     vb[0], vb[1]);
                    mma_bf16(cf[nt], qa[kt2 * 2 + 1], vb[2], vb[3]);
                }
            }
        }
        __syncthreads();
    }

    // ---- epilogue: + bias + residual, fp32 out ----
    const int row0 = m0 + w * 16 + (lane >> 2);
    const int row1 = row0 + 8;
#pragma unroll
    for (int nt = 0; nt < 16; nt++) {
        const int col = n0 + nt * 8 + (lane & 3) * 2;
        const float2 bb = *reinterpret_cast<const float2*>(bo + col);
        const float2 r0 = *reinterpret_cast<const float2*>(
            hs + (size_t)row0 * D_MODEL + col);
        const float2 r1 = *reinterpret_cast<const float2*>(
            hs + (size_t)row1 * D_MODEL + col);
        *reinterpret_cast<float2*>(outp + (size_t)row0 * D_MODEL + col) =
            make_float2(cf[nt][0] + bb.x + r0.x, cf[nt][1] + bb.y + r0.y);
        *reinterpret_cast<float2*>(outp + (size_t)row1 * D_MODEL + col) =
            make_float2(cf[nt][2] + bb.x + r1.x, cf[nt][3] + bb.y + r1.y);
    }
}

// ============================================================================
// Launch
// ============================================================================
extern "C" void kernel_launch(void* const* d_in, const int* in_sizes, int n_in,
                              void* d_out, int out_size)
{
    const float* hs        = (const float*)d_in[0];
    const float* p_out     = (const float*)d_in[1];
    const float* p_out_inv = (const float*)d_in[2];
    const float* Wq        = (const float*)d_in[3];
    const float* Wk        = (const float*)d_in[4];
    const float* Wv        = (const float*)d_in[5];
    const float* Wo        = (const float*)d_in[6];
    const float* bo        = (const float*)d_in[7];
    float* out             = (float*)d_out;

    // >48KB dynamic smem opt-ins (host attributes; idempotent, graph-safe).
    cudaFuncSetAttribute(attn_kernel,
                         cudaFuncAttributeMaxDynamicSharedMemorySize,
                         ATTN_SMEM_BYTES);
    cudaFuncSetAttribute(proj_mma_kernel,
                         cudaFuncAttributeMaxDynamicSharedMemorySize,
                         PROJ_SMEM_BYTES);
    cudaFuncSetAttribute(qkv_mma_kernel,
                         cudaFuncAttributeMaxDynamicSharedMemorySize,
                         QKV_SMEM_BYTES);

    convert_kernel<<<1536, 256>>>(hs, Wq, Wk, Wv, Wo);
    qkv_mma_kernel<<<dim3(8, 32, 3), 256, QKV_SMEM_BYTES>>>(p_out, p_out_inv);
    attn_kernel<<<dim3(64, 8), 128, ATTN_SMEM_BYTES>>>();
    proj_mma_kernel<<<dim3(4, 32), 256, PROJ_SMEM_BYTES>>>(bo, hs, out);
}